// round 4
// baseline (speedup 1.0000x reference)
#include <cuda_runtime.h>
#include <cuda_bf16.h>
#include <math.h>

#define B_  256
#define T_  500
#define BT_ 128000
#define DK_ 128
#define DV_ 256
#define M_  50
#define LW_ 52    // padded row stride of softmax weights
#define KF_ 384   // DV + DK

// ---------------- scratch ----------------
__device__ unsigned g_EA[(size_t)BT_ * DV_];          // (e,a) bf16x2 per (row,d)
__device__ float g_Wt[(size_t)BT_ * LW_];
__device__ __nv_bfloat16 g_READ[(size_t)BT_ * DV_];   // scan output, bf16
__device__ float g_part[2 * (BT_ / 128)];

// ---------------- helpers ----------------
__device__ __forceinline__ unsigned pack_bf16(float lo, float hi) {
  unsigned r;
  asm("cvt.rn.bf16x2.f32 %0, %1, %2;" : "=r"(r) : "f"(hi), "f"(lo));
  return r;
}
__device__ __forceinline__ void mma_bf16(float* c, const unsigned* a, const unsigned* b) {
  asm volatile(
      "mma.sync.aligned.m16n8k16.row.col.f32.bf16.bf16.f32 "
      "{%0,%1,%2,%3}, {%4,%5,%6,%7}, {%8,%9}, {%0,%1,%2,%3};\n"
      : "+f"(c[0]), "+f"(c[1]), "+f"(c[2]), "+f"(c[3])
      : "r"(a[0]), "r"(a[1]), "r"(a[2]), "r"(a[3]), "r"(b[0]), "r"(b[1]));
}
// pair j (bf16 values 2j,2j+1) -> slot 2*(j&3)+(j>>2): a thread's uint2 at
// slot 2c holds pairs {c, c+4}.
__host__ __device__ __forceinline__ constexpr int ppos(int j) {
  return 2 * (j & 3) + (j >> 2);
}
__device__ __forceinline__ unsigned long long pack2(float lo, float hi) {
  unsigned long long r;
  asm("mov.b64 %0, {%1,%2};" : "=l"(r) : "f"(lo), "f"(hi));
  return r;
}
__device__ __forceinline__ unsigned long long fma2(unsigned long long a,
                                                   unsigned long long b,
                                                   unsigned long long c) {
  unsigned long long d;
  asm("fma.rn.f32x2 %0, %1, %2, %3;" : "=l"(d) : "l"(a), "l"(b), "l"(c));
  return d;
}
__device__ __forceinline__ float2 unpack2(unsigned long long v) {
  float2 f;
  asm("mov.b64 {%0,%1}, %2;" : "=f"(f.x), "=f"(f.y) : "l"(v));
  return f;
}

// ================= bf16 GEMM: E and A fused (grid.x: 0,1 -> E; 2,3 -> A) =====
// writes interleaved bf16 (e at halfword 0, a at halfword 1) of g_EA
__global__ void __launch_bounds__(256) gemm_ea_bf16(
    const float* __restrict__ tab, const int* __restrict__ idx,
    const float* __restrict__ We, const float* __restrict__ be,
    const float* __restrict__ Wa, const float* __restrict__ ba) {
  constexpr int BM = 128, BK = 16, K = 256, KT = K / BK;
  constexpr int MT = 4, NT = 4;  // warp tile 64x32, warp grid 2x4

  __shared__ unsigned As[BM][10];
  __shared__ unsigned Bs[128][10];
  __shared__ int rowA[BM];

  const int tid = threadIdx.x;
  const int wid = tid >> 5, lane = tid & 31;
  const int wm = wid >> 2, wn = wid & 3;
  const int r = lane >> 2, c = lane & 3;
  const int bm = blockIdx.y * BM;

  const int half = blockIdx.x >> 1;  // 0=E, 1=A
  const int sub = blockIdx.x & 1;
  const float* W = half ? Wa : We;
  const float* bias = half ? ba : be;
  const int nrow0 = sub * 128;
  __nv_bfloat16* outh = ((__nv_bfloat16*)g_EA) + half;

  for (int i = tid; i < BM; i += 256) rowA[i] = idx[bm + i];
  __syncthreads();

  float acc[MT][NT][4];
#pragma unroll
  for (int i = 0; i < MT; i++)
#pragma unroll
    for (int j = 0; j < NT; j++)
#pragma unroll
      for (int q = 0; q < 4; q++) acc[i][j][q] = 0.f;

  const int fi0 = tid >> 2, kq0 = tid & 3;

  auto loadT = [&](int kt, float4* a4, float4* b4) {
    int k0 = kt * BK;
    a4[0] = *(const float4*)(tab + (size_t)rowA[fi0] * K + k0 + kq0 * 4);
    a4[1] = *(const float4*)(tab + (size_t)rowA[fi0 + 64] * K + k0 + kq0 * 4);
    b4[0] = *(const float4*)(W + (size_t)(nrow0 + fi0) * K + k0 + kq0 * 4);
    b4[1] = *(const float4*)(W + (size_t)(nrow0 + fi0 + 64) * K + k0 + kq0 * 4);
  };
  auto storeT = [&](const float4* a4, const float4* b4) {
#pragma unroll
    for (int v = 0; v < 2; v++) {
      int i = fi0 + v * 64;
      float4 x = a4[v];
      As[i][ppos(2 * kq0)] = pack_bf16(x.x, x.y);
      As[i][ppos(2 * kq0 + 1)] = pack_bf16(x.z, x.w);
      float4 y = b4[v];
      Bs[i][ppos(2 * kq0)] = pack_bf16(y.x, y.y);
      Bs[i][ppos(2 * kq0 + 1)] = pack_bf16(y.z, y.w);
    }
  };

  float4 ra[2], rb[2];
  loadT(0, ra, rb);
  storeT(ra, rb);
  __syncthreads();

  for (int kt = 0; kt < KT; kt++) {
    float4 na[2], nb[2];
    if (kt + 1 < KT) loadT(kt + 1, na, nb);
    unsigned af[MT][4], bf[NT][2];
#pragma unroll
    for (int mt = 0; mt < MT; mt++) {
      int m = wm * 64 + mt * 16 + r;
      uint2 lo = *(const uint2*)&As[m][2 * c];
      uint2 hi = *(const uint2*)&As[m + 8][2 * c];
      af[mt][0] = lo.x; af[mt][2] = lo.y;
      af[mt][1] = hi.x; af[mt][3] = hi.y;
    }
#pragma unroll
    for (int nt = 0; nt < NT; nt++) {
      int n = wn * 32 + nt * 8 + r;
      uint2 bb = *(const uint2*)&Bs[n][2 * c];
      bf[nt][0] = bb.x; bf[nt][1] = bb.y;
    }
#pragma unroll
    for (int mt = 0; mt < MT; mt++)
#pragma unroll
      for (int nt = 0; nt < NT; nt++) mma_bf16(acc[mt][nt], af[mt], bf[nt]);
    if (kt + 1 < KT) {
      __syncthreads();
      storeT(na, nb);
      __syncthreads();
    }
  }

#pragma unroll
  for (int mt = 0; mt < MT; mt++) {
#pragma unroll
    for (int nt = 0; nt < NT; nt++) {
      int rowL = wm * 64 + mt * 16 + r;
      int ncol = nrow0 + wn * 32 + nt * 8 + 2 * c;
      float b0 = bias[ncol], b1 = bias[ncol + 1];
      float t0 = acc[mt][nt][0] + b0, t1 = acc[mt][nt][1] + b1;
      float t2 = acc[mt][nt][2] + b0, t3 = acc[mt][nt][3] + b1;
      if (half == 0) {
        t0 = 1.f / (1.f + expf(-t0)); t1 = 1.f / (1.f + expf(-t1));
        t2 = 1.f / (1.f + expf(-t2)); t3 = 1.f / (1.f + expf(-t3));
      } else {
        t0 = tanhf(t0); t1 = tanhf(t1); t2 = tanhf(t2); t3 = tanhf(t3);
      }
      size_t r0 = ((size_t)(bm + rowL) * DV_ + ncol) * 2;
      size_t r1 = ((size_t)(bm + rowL + 8) * DV_ + ncol) * 2;
      outh[r0] = __float2bfloat16(t0);
      outh[r0 + 2] = __float2bfloat16(t1);
      outh[r1] = __float2bfloat16(t2);
      outh[r1 + 2] = __float2bfloat16(t3);
    }
  }
}

// ================= bf16 logits GEMM + fused softmax =================
__global__ void __launch_bounds__(256) logits_softmax_bf16(
    const float* __restrict__ q_tab, const int* __restrict__ q_data,
    const float* __restrict__ Mk) {
  constexpr int BM = 128, BK = 16, K = 128, KT = K / BK;
  constexpr int MT = 2, NT = 4;

  __shared__ unsigned As[BM][10];
  __shared__ unsigned Bs[64][10];
  __shared__ int rowA[BM];
  __shared__ float sLg[BM][65];
  __shared__ float sInv[BM];

  const int tid = threadIdx.x;
  const int wid = tid >> 5, lane = tid & 31;
  const int wm = wid >> 1, wn = wid & 1;
  const int r = lane >> 2, c = lane & 3;
  const int bm = blockIdx.x * BM;

  for (int i = tid; i < BM; i += 256) rowA[i] = q_data[bm + i];
  __syncthreads();

  float acc[MT][NT][4];
#pragma unroll
  for (int i = 0; i < MT; i++)
#pragma unroll
    for (int j = 0; j < NT; j++)
#pragma unroll
      for (int q = 0; q < 4; q++) acc[i][j][q] = 0.f;

  const int fi0 = tid >> 2, kq0 = tid & 3;
  const bool bAct = fi0 < 50;

  auto loadT = [&](int kt, float4* a4, float4* b4) {
    int k0 = kt * BK;
    a4[0] = *(const float4*)(q_tab + (size_t)rowA[fi0] * K + k0 + kq0 * 4);
    a4[1] = *(const float4*)(q_tab + (size_t)rowA[fi0 + 64] * K + k0 + kq0 * 4);
    b4[0] = bAct ? *(const float4*)(Mk + (size_t)fi0 * K + k0 + kq0 * 4)
                 : make_float4(0.f, 0.f, 0.f, 0.f);
  };
  auto storeT = [&](const float4* a4, const float4* b4) {
#pragma unroll
    for (int v = 0; v < 2; v++) {
      int i = fi0 + v * 64;
      float4 x = a4[v];
      As[i][ppos(2 * kq0)] = pack_bf16(x.x, x.y);
      As[i][ppos(2 * kq0 + 1)] = pack_bf16(x.z, x.w);
    }
    float4 y = b4[0];
    Bs[fi0][ppos(2 * kq0)] = pack_bf16(y.x, y.y);
    Bs[fi0][ppos(2 * kq0 + 1)] = pack_bf16(y.z, y.w);
  };

  float4 ra[2], rb[1];
  loadT(0, ra, rb);
  storeT(ra, rb);
  __syncthreads();

  for (int kt = 0; kt < KT; kt++) {
    float4 na[2], nb[1];
    if (kt + 1 < KT) loadT(kt + 1, na, nb);
    unsigned af[MT][4], bf[NT][2];
#pragma unroll
    for (int mt = 0; mt < MT; mt++) {
      int m = wm * 32 + mt * 16 + r;
      uint2 lo = *(const uint2*)&As[m][2 * c];
      uint2 hi = *(const uint2*)&As[m + 8][2 * c];
      af[mt][0] = lo.x; af[mt][2] = lo.y;
      af[mt][1] = hi.x; af[mt][3] = hi.y;
    }
#pragma unroll
    for (int nt = 0; nt < NT; nt++) {
      int n = wn * 32 + nt * 8 + r;
      uint2 bb = *(const uint2*)&Bs[n][2 * c];
      bf[nt][0] = bb.x; bf[nt][1] = bb.y;
    }
#pragma unroll
    for (int mt = 0; mt < MT; mt++)
#pragma unroll
      for (int nt = 0; nt < NT; nt++) mma_bf16(acc[mt][nt], af[mt], bf[nt]);
    if (kt + 1 < KT) {
      __syncthreads();
      storeT(na, nb);
      __syncthreads();
    }
  }

#pragma unroll
  for (int mt = 0; mt < MT; mt++) {
#pragma unroll
    for (int nt = 0; nt < NT; nt++) {
      int rowL = wm * 32 + mt * 16 + r;
      int colL = wn * 32 + nt * 8 + 2 * c;
      sLg[rowL][colL] = acc[mt][nt][0];
      sLg[rowL][colL + 1] = acc[mt][nt][1];
      sLg[rowL + 8][colL] = acc[mt][nt][2];
      sLg[rowL + 8][colL + 1] = acc[mt][nt][3];
    }
  }
  __syncthreads();

  if (tid < BM) {
    float mx = -1e30f;
#pragma unroll 10
    for (int j = 0; j < M_; j++) mx = fmaxf(mx, sLg[tid][j]);
    float s = 0.f;
#pragma unroll 10
    for (int j = 0; j < M_; j++) {
      float ev = expf(sLg[tid][j] - mx);
      sLg[tid][j] = ev;
      s += ev;
    }
    sInv[tid] = 1.f / s;
  }
  __syncthreads();

  for (int f = tid; f < BM * LW_; f += 256) {
    int rowL = f / LW_;
    int j = f - rowL * LW_;
    float v = (j < M_) ? sLg[rowL][j] * sInv[rowL] : 0.f;
    g_Wt[(size_t)(bm + rowL) * LW_ + j] = v;
  }
}

// ---------------- scan: one CTA per batch element, barrier-free ----------------
__global__ void __launch_bounds__(256) scan_kernel(
    const float* __restrict__ Mv0, const int* __restrict__ q_data) {
  const int b = blockIdx.x;
  const int d = threadIdx.x;
  const int wid = d >> 5, lane = d & 31;
  __shared__ __align__(16) float ws_all[8][64];
  float* ws = ws_all[wid];

  unsigned long long mv[M_ / 2];
#pragma unroll
  for (int i = 0; i < M_ / 2; i++)
    mv[i] = pack2(Mv0[(2 * i) * DV_ + d], Mv0[(2 * i + 1) * DV_ + d]);

  const size_t row0 = (size_t)b * T_;
  const __nv_bfloat162* EA = (const __nv_bfloat162*)g_EA;
  float2 ea0 = __bfloat1622float2(EA[row0 * DV_ + d]);
  float e = ea0.x, a = ea0.y;
  int qi = q_data[row0];
  if (lane < 13)
    *(float4*)&ws[lane * 4] = *(const float4*)(g_Wt + row0 * LW_ + lane * 4);

  for (int t = 0; t < T_; t++) {
    const size_t row = row0 + t;
    const size_t rn = row0 + (t + 1 < T_ ? t + 1 : t);
    float2 ean = __bfloat1622float2(EA[rn * DV_ + d]);
    int qi2 = q_data[rn];
    float4 wv;
    if (lane < 13) wv = *(const float4*)(g_Wt + rn * LW_ + lane * 4);

    unsigned long long rd0 = 0ULL, rd1 = 0ULL;
    if (qi >= 1) {
      unsigned long long ne2 = pack2(-e, -e);
      unsigned long long ad2 = pack2(a, a);
#pragma unroll
      for (int j = 0; j < 12; j++) {
        ulonglong2 wp = *(const ulonglong2*)&ws[4 * j];
        rd0 = fma2(wp.x, mv[2 * j], rd0);
        unsigned long long t0 = fma2(mv[2 * j], ne2, ad2);
        mv[2 * j] = fma2(wp.x, t0, mv[2 * j]);
        rd1 = fma2(wp.y, mv[2 * j + 1], rd1);
        unsigned long long t1 = fma2(mv[2 * j + 1], ne2, ad2);
        mv[2 * j + 1] = fma2(wp.y, t1, mv[2 * j + 1]);
      }
      unsigned long long wl = *(const unsigned long long*)&ws[48];
      rd0 = fma2(wl, mv[24], rd0);
      unsigned long long tl = fma2(mv[24], ne2, ad2);
      mv[24] = fma2(wl, tl, mv[24]);
    } else {
#pragma unroll
      for (int j = 0; j < 12; j++) {
        ulonglong2 wp = *(const ulonglong2*)&ws[4 * j];
        rd0 = fma2(wp.x, mv[2 * j], rd0);
        rd1 = fma2(wp.y, mv[2 * j + 1], rd1);
      }
      unsigned long long wl = *(const unsigned long long*)&ws[48];
      rd0 = fma2(wl, mv[24], rd0);
    }
    float2 s0 = unpack2(rd0), s1 = unpack2(rd1);
    g_READ[row * DV_ + d] = __float2bfloat16((s0.x + s0.y) + (s1.x + s1.y));

    if (lane < 13) *(float4*)&ws[lane * 4] = wv;
    e = ean.x; a = ean.y; qi = qi2;
  }
}

// ================= final bf16 GEMM (A = [READ | q_e]) + fused head =======
__global__ void __launch_bounds__(256) final_bf16(
    const float* __restrict__ q_tab, const int* __restrict__ q_data,
    const float* __restrict__ Wr, const float* __restrict__ br,
    const float* __restrict__ Wp, const float* __restrict__ bp,
    const float* __restrict__ target, float* __restrict__ out_probs) {
  constexpr int BM = 128, BK = 16, K = KF_, KT = K / BK;
  constexpr int MT = 2, NT = 8;  // warp tile 32x64, warp grid 4x2

  __shared__ unsigned As[BM][10];
  __shared__ unsigned Bs[128][10];
  __shared__ int rowA[BM];
  __shared__ float sBr[128], sWp[128];
  __shared__ float red[128][2];
  __shared__ float sl[128], sv[128];

  const int tid = threadIdx.x;
  const int wid = tid >> 5, lane = tid & 31;
  const int wm = wid >> 1, wn = wid & 1;
  const int r = lane >> 2, c = lane & 3;
  const int bm = blockIdx.y * BM;

  if (tid < 128) { sBr[tid] = br[tid]; sWp[tid] = Wp[tid]; }
  for (int i = tid; i < BM; i += 256) rowA[i] = q_data[bm + i];
  __syncthreads();

  float acc[MT][NT][4];
#pragma unroll
  for (int i = 0; i < MT; i++)
#pragma unroll
    for (int j = 0; j < NT; j++)
#pragma unroll
      for (int q = 0; q < 4; q++) acc[i][j][q] = 0.f;

  const int fi0 = tid >> 2, kq0 = tid & 3;

  // per kt: A 4 bf16 per thread-slot (uint2 from READ or packed from q_tab)
  auto loadA1 = [&](int fi, int kk) -> uint2 {
    if (kk < DV_)
      return *(const uint2*)(g_READ + (size_t)(bm + fi) * DV_ + kk);
    float4 x = *(const float4*)(q_tab + (size_t)rowA[fi] * DK_ + (kk - DV_));
    return make_uint2(pack_bf16(x.x, x.y), pack_bf16(x.z, x.w));
  };
  auto loadT = [&](int kt, uint2* a2, float4* b4) {
    int kk = kt * BK + kq0 * 4;
    a2[0] = loadA1(fi0, kk);
    a2[1] = loadA1(fi0 + 64, kk);
    b4[0] = *(const float4*)(Wr + (size_t)fi0 * K + kk);
    b4[1] = *(const float4*)(Wr + (size_t)(fi0 + 64) * K + kk);
  };
  auto storeT = [&](const uint2* a2, const float4* b4) {
#pragma unroll
    for (int v = 0; v < 2; v++) {
      int i = fi0 + v * 64;
      As[i][ppos(2 * kq0)] = a2[v].x;
      As[i][ppos(2 * kq0 + 1)] = a2[v].y;
      float4 y = b4[v];
      Bs[i][ppos(2 * kq0)] = pack_bf16(y.x, y.y);
      Bs[i][ppos(2 * kq0 + 1)] = pack_bf16(y.z, y.w);
    }
  };

  uint2 ra[2];
  float4 rb[2];
  loadT(0, ra, rb);
  storeT(ra, rb);
  __syncthreads();

  for (int kt = 0; kt < KT; kt++) {
    uint2 na[2];
    float4 nb[2];
    if (kt + 1 < KT) loadT(kt + 1, na, nb);
    unsigned af[MT][4], bf[NT][2];
#pragma unroll
    for (int mt = 0; mt < MT; mt++) {
      int m = wm * 32 + mt * 16 + r;
      uint2 lo = *(const uint2*)&As[m][2 * c];
      uint2 hi = *(const uint2*)&As[m + 8][2 * c];
      af[mt][0] = lo.x; af[mt][2] = lo.y;
      af[mt][1] = hi.x; af[mt][3] = hi.y;
    }
#pragma unroll
    for (int nt = 0; nt < NT; nt++) {
      int n = wn * 64 + nt * 8 + r;
      uint2 bb = *(const uint2*)&Bs[n][2 * c];
      bf[nt][0] = bb.x; bf[nt][1] = bb.y;
    }
#pragma unroll
    for (int mt = 0; mt < MT; mt++)
#pragma unroll
      for (int nt = 0; nt < NT; nt++) mma_bf16(acc[mt][nt], af[mt], bf[nt]);
    if (kt + 1 < KT) {
      __syncthreads();
      storeT(na, nb);
      __syncthreads();
    }
  }
  __syncthreads();

  float ps[4] = {0.f, 0.f, 0.f, 0.f};
#pragma unroll
  for (int nt = 0; nt < NT; nt++) {
#pragma unroll
    for (int j = 0; j < 2; j++) {
      int n = wn * 64 + nt * 8 + 2 * c + j;
      float bb = sBr[n], wp = sWp[n];
#pragma unroll
      for (int mt = 0; mt < MT; mt++) {
        float h0 = tanhf(acc[mt][nt][j] + bb);
        float h1 = tanhf(acc[mt][nt][2 + j] + bb);
        ps[mt * 2 + 0] = fmaf(h0, wp, ps[mt * 2 + 0]);
        ps[mt * 2 + 1] = fmaf(h1, wp, ps[mt * 2 + 1]);
      }
    }
  }
#pragma unroll
  for (int off = 1; off <= 2; off <<= 1)
#pragma unroll
    for (int i = 0; i < 4; i++) ps[i] += __shfl_xor_sync(0xffffffffu, ps[i], off);
  if (c == 0) {
#pragma unroll
    for (int mt = 0; mt < MT; mt++)
#pragma unroll
      for (int hf = 0; hf < 2; hf++)
        red[wm * 32 + mt * 16 + r + hf * 8][wn] = ps[mt * 2 + hf];
  }
  __syncthreads();

  float per = 0.f, val = 0.f;
  if (tid < 128) {
    float p = bp[0] + red[tid][0] + red[tid][1];
    size_t row = (size_t)bm + tid;
    out_probs[row] = 1.f / (1.f + expf(-p));
    float tg = target[row];
    if (tg >= 0.f) {
      per = fmaxf(p, 0.f) - p * tg + log1pf(expf(-fabsf(p)));
      val = 1.f;
    }
  }
  __syncthreads();
  if (tid < 128) { sl[tid] = per; sv[tid] = val; }
  __syncthreads();
  for (int s = 64; s > 0; s >>= 1) {
    if (tid < s) { sl[tid] += sl[tid + s]; sv[tid] += sv[tid + s]; }
    __syncthreads();
  }
  if (tid == 0) {
    g_part[2 * blockIdx.y] = sl[0];
    g_part[2 * blockIdx.y + 1] = sv[0];
  }
}

// ---------------- final loss reduction ----------------
__global__ void __launch_bounds__(256) finalize_kernel(float* __restrict__ out) {
  __shared__ float sl[256], sv[256];
  int tid = threadIdx.x;
  float l = 0.f, v = 0.f;
  for (int i = tid; i < BT_ / 128; i += 256) {
    l += g_part[2 * i];
    v += g_part[2 * i + 1];
  }
  sl[tid] = l; sv[tid] = v;
  __syncthreads();
  for (int s = 128; s > 0; s >>= 1) {
    if (tid < s) { sl[tid] += sl[tid + s]; sv[tid] += sv[tid + s]; }
    __syncthreads();
  }
  if (tid == 0) out[0] = sl[0] / fmaxf(sv[0], 1.f);
}

// ---------------- launch ----------------
extern "C" void kernel_launch(void* const* d_in, const int* in_sizes, int n_in,
                              void* d_out, int out_size) {
  const int* q_data = (const int*)d_in[0];
  const int* qa_data = (const int*)d_in[1];
  const float* target = (const float*)d_in[2];
  const float* q_tab = (const float*)d_in[3];
  const float* qa_tab = (const float*)d_in[4];
  const float* Mk = (const float*)d_in[5];
  const float* Mv0 = (const float*)d_in[6];
  const float* We = (const float*)d_in[7];
  const float* be = (const float*)d_in[8];
  const float* Wa = (const float*)d_in[9];
  const float* ba = (const float*)d_in[10];
  const float* Wr = (const float*)d_in[11];
  const float* br = (const float*)d_in[12];
  const float* Wp = (const float*)d_in[13];
  const float* bp = (const float*)d_in[14];
  float* out = (float*)d_out;

  logits_softmax_bf16<<<BT_ / 128, 256>>>(q_tab, q_data, Mk);
  gemm_ea_bf16<<<dim3(4, BT_ / 128), 256>>>(qa_tab, qa_data, We, be, Wa, ba);
  scan_kernel<<<B_, 256>>>(Mv0, q_data);
  final_bf16<<<dim3(1, BT_ / 128), 256>>>(q_tab, q_data, Wr, br, Wp, bp, target,
                                          out + 1);
  finalize_kernel<<<1, 256>>>(out);
}

// round 5
// speedup vs baseline: 1.0348x; 1.0348x over previous
#include <cuda_runtime.h>
#include <cuda_bf16.h>
#include <math.h>

#define B_  256
#define T_  500
#define BT_ 128000
#define DK_ 128
#define DV_ 256
#define M_  50
#define LW_ 52    // padded row stride of softmax weights
#define KF_ 384   // DV + DK

// ---------------- scratch ----------------
__device__ unsigned g_EA[(size_t)BT_ * DV_];          // (e,a) bf16x2 per (row,d)
__device__ float g_Wt[(size_t)BT_ * LW_];
__device__ __nv_bfloat16 g_READ[(size_t)BT_ * DV_];   // scan output, bf16
__device__ float g_part[2 * (BT_ / 128)];

// ---------------- helpers ----------------
__device__ __forceinline__ unsigned pack_bf16(float lo, float hi) {
  unsigned r;
  asm("cvt.rn.bf16x2.f32 %0, %1, %2;" : "=r"(r) : "f"(hi), "f"(lo));
  return r;
}
__device__ __forceinline__ void mma_bf16(float* c, const unsigned* a, const unsigned* b) {
  asm volatile(
      "mma.sync.aligned.m16n8k16.row.col.f32.bf16.bf16.f32 "
      "{%0,%1,%2,%3}, {%4,%5,%6,%7}, {%8,%9}, {%0,%1,%2,%3};\n"
      : "+f"(c[0]), "+f"(c[1]), "+f"(c[2]), "+f"(c[3])
      : "r"(a[0]), "r"(a[1]), "r"(a[2]), "r"(a[3]), "r"(b[0]), "r"(b[1]));
}
// pair j (bf16 values 2j,2j+1) -> slot 2*(j&3)+(j>>2): a thread's uint2 at
// slot 2c holds pairs {c, c+4}.
__host__ __device__ __forceinline__ constexpr int ppos(int j) {
  return 2 * (j & 3) + (j >> 2);
}
__device__ __forceinline__ unsigned long long pack2(float lo, float hi) {
  unsigned long long r;
  asm("mov.b64 %0, {%1,%2};" : "=l"(r) : "f"(lo), "f"(hi));
  return r;
}
__device__ __forceinline__ unsigned long long fma2(unsigned long long a,
                                                   unsigned long long b,
                                                   unsigned long long c) {
  unsigned long long d;
  asm("fma.rn.f32x2 %0, %1, %2, %3;" : "=l"(d) : "l"(a), "l"(b), "l"(c));
  return d;
}
__device__ __forceinline__ float2 unpack2(unsigned long long v) {
  float2 f;
  asm("mov.b64 {%0,%1}, %2;" : "=f"(f.x), "=f"(f.y) : "l"(v));
  return f;
}

// ================= bf16 GEMM: E and A in ONE block, packed bf16x2 out =====
// Each block: 128 rows x 64 cols, computes e=sigmoid(qa@We^T+be) and
// a=tanh(qa@Wa^T+ba) on the shared A tile, stores pack(e,a) -> g_EA.
__global__ void __launch_bounds__(256) gemm_ea_bf16(
    const float* __restrict__ tab, const int* __restrict__ idx,
    const float* __restrict__ We, const float* __restrict__ be,
    const float* __restrict__ Wa, const float* __restrict__ ba) {
  constexpr int BM = 128, BK = 16, K = 256, KT = K / BK;
  constexpr int MT = 4, NT = 2;  // warp tile 64x16 per matrix, warp grid 2x4

  __shared__ unsigned As[BM][10];
  __shared__ unsigned Bse[64][10];
  __shared__ unsigned Bsa[64][10];
  __shared__ int rowA[BM];

  const int tid = threadIdx.x;
  const int wid = tid >> 5, lane = tid & 31;
  const int wm = wid >> 2, wn = wid & 3;  // 2 x 4
  const int r = lane >> 2, c = lane & 3;
  const int bm = blockIdx.y * BM;
  const int nrow0 = blockIdx.x * 64;  // 64-col slab

  for (int i = tid; i < BM; i += 256) rowA[i] = idx[bm + i];
  __syncthreads();

  float accE[MT][NT][4], accA[MT][NT][4];
#pragma unroll
  for (int i = 0; i < MT; i++)
#pragma unroll
    for (int j = 0; j < NT; j++)
#pragma unroll
      for (int q = 0; q < 4; q++) { accE[i][j][q] = 0.f; accA[i][j][q] = 0.f; }

  const int fi0 = tid >> 2, kq0 = tid & 3;

  auto loadT = [&](int kt, float4* a4, float4* b4) {
    int k0 = kt * BK + kq0 * 4;
    a4[0] = *(const float4*)(tab + (size_t)rowA[fi0] * K + k0);
    a4[1] = *(const float4*)(tab + (size_t)rowA[fi0 + 64] * K + k0);
    b4[0] = *(const float4*)(We + (size_t)(nrow0 + fi0) * K + k0);
    b4[1] = *(const float4*)(Wa + (size_t)(nrow0 + fi0) * K + k0);
  };
  auto storeT = [&](const float4* a4, const float4* b4) {
#pragma unroll
    for (int v = 0; v < 2; v++) {
      int i = fi0 + v * 64;
      float4 x = a4[v];
      As[i][ppos(2 * kq0)] = pack_bf16(x.x, x.y);
      As[i][ppos(2 * kq0 + 1)] = pack_bf16(x.z, x.w);
    }
    float4 y = b4[0];
    Bse[fi0][ppos(2 * kq0)] = pack_bf16(y.x, y.y);
    Bse[fi0][ppos(2 * kq0 + 1)] = pack_bf16(y.z, y.w);
    float4 z = b4[1];
    Bsa[fi0][ppos(2 * kq0)] = pack_bf16(z.x, z.y);
    Bsa[fi0][ppos(2 * kq0 + 1)] = pack_bf16(z.z, z.w);
  };

  float4 ra[2], rb[2];
  loadT(0, ra, rb);
  storeT(ra, rb);
  __syncthreads();

  for (int kt = 0; kt < KT; kt++) {
    float4 na[2], nb[2];
    if (kt + 1 < KT) loadT(kt + 1, na, nb);
    unsigned af[MT][4], bfe[NT][2], bfa[NT][2];
#pragma unroll
    for (int mt = 0; mt < MT; mt++) {
      int m = wm * 64 + mt * 16 + r;
      uint2 lo = *(const uint2*)&As[m][2 * c];
      uint2 hi = *(const uint2*)&As[m + 8][2 * c];
      af[mt][0] = lo.x; af[mt][2] = lo.y;
      af[mt][1] = hi.x; af[mt][3] = hi.y;
    }
#pragma unroll
    for (int nt = 0; nt < NT; nt++) {
      int n = wn * 16 + nt * 8 + r;
      uint2 ee = *(const uint2*)&Bse[n][2 * c];
      bfe[nt][0] = ee.x; bfe[nt][1] = ee.y;
      uint2 aa = *(const uint2*)&Bsa[n][2 * c];
      bfa[nt][0] = aa.x; bfa[nt][1] = aa.y;
    }
#pragma unroll
    for (int mt = 0; mt < MT; mt++)
#pragma unroll
      for (int nt = 0; nt < NT; nt++) {
        mma_bf16(accE[mt][nt], af[mt], bfe[nt]);
        mma_bf16(accA[mt][nt], af[mt], bfa[nt]);
      }
    if (kt + 1 < KT) {
      __syncthreads();
      storeT(na, nb);
      __syncthreads();
    }
  }

  // epilogue: e=sigmoid, a=tanh, pack (e,a) -> one uint per (row,col)
#pragma unroll
  for (int mt = 0; mt < MT; mt++) {
#pragma unroll
    for (int nt = 0; nt < NT; nt++) {
      int rowL = wm * 64 + mt * 16 + r;
      int ncol = nrow0 + wn * 16 + nt * 8 + 2 * c;
      float be0 = be[ncol], be1 = be[ncol + 1];
      float ba0 = ba[ncol], ba1 = ba[ncol + 1];
      float e0 = 1.f / (1.f + expf(-(accE[mt][nt][0] + be0)));
      float e1 = 1.f / (1.f + expf(-(accE[mt][nt][1] + be1)));
      float e2 = 1.f / (1.f + expf(-(accE[mt][nt][2] + be0)));
      float e3 = 1.f / (1.f + expf(-(accE[mt][nt][3] + be1)));
      float a0 = tanhf(accA[mt][nt][0] + ba0);
      float a1 = tanhf(accA[mt][nt][1] + ba1);
      float a2 = tanhf(accA[mt][nt][2] + ba0);
      float a3 = tanhf(accA[mt][nt][3] + ba1);
      uint2 v0 = make_uint2(pack_bf16(e0, a0), pack_bf16(e1, a1));
      uint2 v1 = make_uint2(pack_bf16(e2, a2), pack_bf16(e3, a3));
      *(uint2*)(g_EA + (size_t)(bm + rowL) * DV_ + ncol) = v0;
      *(uint2*)(g_EA + (size_t)(bm + rowL + 8) * DV_ + ncol) = v1;
    }
  }
}

// ================= bf16 logits GEMM + fused softmax =================
__global__ void __launch_bounds__(256) logits_softmax_bf16(
    const float* __restrict__ q_tab, const int* __restrict__ q_data,
    const float* __restrict__ Mk) {
  constexpr int BM = 128, BK = 16, K = 128, KT = K / BK;
  constexpr int MT = 2, NT = 4;

  __shared__ unsigned As[BM][10];
  __shared__ unsigned Bs[64][10];
  __shared__ int rowA[BM];
  __shared__ float sLg[BM][65];
  __shared__ float sInv[BM];

  const int tid = threadIdx.x;
  const int wid = tid >> 5, lane = tid & 31;
  const int wm = wid >> 1, wn = wid & 1;
  const int r = lane >> 2, c = lane & 3;
  const int bm = blockIdx.x * BM;

  for (int i = tid; i < BM; i += 256) rowA[i] = q_data[bm + i];
  __syncthreads();

  float acc[MT][NT][4];
#pragma unroll
  for (int i = 0; i < MT; i++)
#pragma unroll
    for (int j = 0; j < NT; j++)
#pragma unroll
      for (int q = 0; q < 4; q++) acc[i][j][q] = 0.f;

  const int fi0 = tid >> 2, kq0 = tid & 3;
  const bool bAct = fi0 < 50;

  auto loadT = [&](int kt, float4* a4, float4* b4) {
    int k0 = kt * BK;
    a4[0] = *(const float4*)(q_tab + (size_t)rowA[fi0] * K + k0 + kq0 * 4);
    a4[1] = *(const float4*)(q_tab + (size_t)rowA[fi0 + 64] * K + k0 + kq0 * 4);
    b4[0] = bAct ? *(const float4*)(Mk + (size_t)fi0 * K + k0 + kq0 * 4)
                 : make_float4(0.f, 0.f, 0.f, 0.f);
  };
  auto storeT = [&](const float4* a4, const float4* b4) {
#pragma unroll
    for (int v = 0; v < 2; v++) {
      int i = fi0 + v * 64;
      float4 x = a4[v];
      As[i][ppos(2 * kq0)] = pack_bf16(x.x, x.y);
      As[i][ppos(2 * kq0 + 1)] = pack_bf16(x.z, x.w);
    }
    float4 y = b4[0];
    Bs[fi0][ppos(2 * kq0)] = pack_bf16(y.x, y.y);
    Bs[fi0][ppos(2 * kq0 + 1)] = pack_bf16(y.z, y.w);
  };

  float4 ra[2], rb[1];
  loadT(0, ra, rb);
  storeT(ra, rb);
  __syncthreads();

  for (int kt = 0; kt < KT; kt++) {
    float4 na[2], nb[1];
    if (kt + 1 < KT) loadT(kt + 1, na, nb);
    unsigned af[MT][4], bf[NT][2];
#pragma unroll
    for (int mt = 0; mt < MT; mt++) {
      int m = wm * 32 + mt * 16 + r;
      uint2 lo = *(const uint2*)&As[m][2 * c];
      uint2 hi = *(const uint2*)&As[m + 8][2 * c];
      af[mt][0] = lo.x; af[mt][2] = lo.y;
      af[mt][1] = hi.x; af[mt][3] = hi.y;
    }
#pragma unroll
    for (int nt = 0; nt < NT; nt++) {
      int n = wn * 32 + nt * 8 + r;
      uint2 bb = *(const uint2*)&Bs[n][2 * c];
      bf[nt][0] = bb.x; bf[nt][1] = bb.y;
    }
#pragma unroll
    for (int mt = 0; mt < MT; mt++)
#pragma unroll
      for (int nt = 0; nt < NT; nt++) mma_bf16(acc[mt][nt], af[mt], bf[nt]);
    if (kt + 1 < KT) {
      __syncthreads();
      storeT(na, nb);
      __syncthreads();
    }
  }

#pragma unroll
  for (int mt = 0; mt < MT; mt++) {
#pragma unroll
    for (int nt = 0; nt < NT; nt++) {
      int rowL = wm * 32 + mt * 16 + r;
      int colL = wn * 32 + nt * 8 + 2 * c;
      sLg[rowL][colL] = acc[mt][nt][0];
      sLg[rowL][colL + 1] = acc[mt][nt][1];
      sLg[rowL + 8][colL] = acc[mt][nt][2];
      sLg[rowL + 8][colL + 1] = acc[mt][nt][3];
    }
  }
  __syncthreads();

  if (tid < BM) {
    float mx = -1e30f;
#pragma unroll 10
    for (int j = 0; j < M_; j++) mx = fmaxf(mx, sLg[tid][j]);
    float s = 0.f;
#pragma unroll 10
    for (int j = 0; j < M_; j++) {
      float ev = expf(sLg[tid][j] - mx);
      sLg[tid][j] = ev;
      s += ev;
    }
    sInv[tid] = 1.f / s;
  }
  __syncthreads();

  for (int f = tid; f < BM * LW_; f += 256) {
    int rowL = f / LW_;
    int j = f - rowL * LW_;
    float v = (j < M_) ? sLg[rowL][j] * sInv[rowL] : 0.f;
    g_Wt[(size_t)(bm + rowL) * LW_ + j] = v;
  }
}

// ---------------- scan: one CTA per batch element, barrier-free ----------------
__global__ void __launch_bounds__(256) scan_kernel(
    const float* __restrict__ Mv0, const int* __restrict__ q_data) {
  const int b = blockIdx.x;
  const int d = threadIdx.x;
  const int wid = d >> 5, lane = d & 31;
  __shared__ __align__(16) float ws_all[8][64];
  float* ws = ws_all[wid];

  unsigned long long mv[M_ / 2];
#pragma unroll
  for (int i = 0; i < M_ / 2; i++)
    mv[i] = pack2(Mv0[(2 * i) * DV_ + d], Mv0[(2 * i + 1) * DV_ + d]);

  const size_t row0 = (size_t)b * T_;
  const __nv_bfloat162* EA = (const __nv_bfloat162*)g_EA;
  float2 ea0 = __bfloat1622float2(EA[row0 * DV_ + d]);
  float e = ea0.x, a = ea0.y;
  int qi = q_data[row0];
  if (lane < 13)
    *(float4*)&ws[lane * 4] = *(const float4*)(g_Wt + row0 * LW_ + lane * 4);

  for (int t = 0; t < T_; t++) {
    const size_t row = row0 + t;
    const size_t rn = row0 + (t + 1 < T_ ? t + 1 : t);
    float2 ean = __bfloat1622float2(EA[rn * DV_ + d]);
    int qi2 = q_data[rn];
    float4 wv;
    if (lane < 13) wv = *(const float4*)(g_Wt + rn * LW_ + lane * 4);

    unsigned long long rd0 = 0ULL, rd1 = 0ULL;
    if (qi >= 1) {
      unsigned long long ne2 = pack2(-e, -e);
      unsigned long long ad2 = pack2(a, a);
#pragma unroll
      for (int j = 0; j < 12; j++) {
        ulonglong2 wp = *(const ulonglong2*)&ws[4 * j];
        rd0 = fma2(wp.x, mv[2 * j], rd0);
        unsigned long long t0 = fma2(mv[2 * j], ne2, ad2);
        mv[2 * j] = fma2(wp.x, t0, mv[2 * j]);
        rd1 = fma2(wp.y, mv[2 * j + 1], rd1);
        unsigned long long t1 = fma2(mv[2 * j + 1], ne2, ad2);
        mv[2 * j + 1] = fma2(wp.y, t1, mv[2 * j + 1]);
      }
      unsigned long long wl = *(const unsigned long long*)&ws[48];
      rd0 = fma2(wl, mv[24], rd0);
      unsigned long long tl = fma2(mv[24], ne2, ad2);
      mv[24] = fma2(wl, tl, mv[24]);
    } else {
#pragma unroll
      for (int j = 0; j < 12; j++) {
        ulonglong2 wp = *(const ulonglong2*)&ws[4 * j];
        rd0 = fma2(wp.x, mv[2 * j], rd0);
        rd1 = fma2(wp.y, mv[2 * j + 1], rd1);
      }
      unsigned long long wl = *(const unsigned long long*)&ws[48];
      rd0 = fma2(wl, mv[24], rd0);
    }
    float2 s0 = unpack2(rd0), s1 = unpack2(rd1);
    g_READ[row * DV_ + d] = __float2bfloat16((s0.x + s0.y) + (s1.x + s1.y));

    if (lane < 13) *(float4*)&ws[lane * 4] = wv;
    e = ean.x; a = ean.y; qi = qi2;
  }
}

// ================= final bf16 GEMM (A = [READ | q_e]) + fused head =======
__global__ void __launch_bounds__(256) final_bf16(
    const float* __restrict__ q_tab, const int* __restrict__ q_data,
    const float* __restrict__ Wr, const float* __restrict__ br,
    const float* __restrict__ Wp, const float* __restrict__ bp,
    const float* __restrict__ target, float* __restrict__ out_probs) {
  constexpr int BM = 128, BK = 16, K = KF_, KT = K / BK;
  constexpr int MT = 2, NT = 8;  // warp tile 32x64, warp grid 4x2

  __shared__ unsigned As[BM][10];
  __shared__ unsigned Bs[128][10];
  __shared__ int rowA[BM];
  __shared__ float sBr[128], sWp[128];
  __shared__ float red[128][2];
  __shared__ float sl[128], sv[128];

  const int tid = threadIdx.x;
  const int wid = tid >> 5, lane = tid & 31;
  const int wm = wid >> 1, wn = wid & 1;
  const int r = lane >> 2, c = lane & 3;
  const int bm = blockIdx.y * BM;

  if (tid < 128) { sBr[tid] = br[tid]; sWp[tid] = Wp[tid]; }
  for (int i = tid; i < BM; i += 256) rowA[i] = q_data[bm + i];
  __syncthreads();

  float acc[MT][NT][4];
#pragma unroll
  for (int i = 0; i < MT; i++)
#pragma unroll
    for (int j = 0; j < NT; j++)
#pragma unroll
      for (int q = 0; q < 4; q++) acc[i][j][q] = 0.f;

  const int fi0 = tid >> 2, kq0 = tid & 3;

  auto loadA1 = [&](int fi, int kk) -> uint2 {
    if (kk < DV_)
      return *(const uint2*)(g_READ + (size_t)(bm + fi) * DV_ + kk);
    float4 x = *(const float4*)(q_tab + (size_t)rowA[fi] * DK_ + (kk - DV_));
    return make_uint2(pack_bf16(x.x, x.y), pack_bf16(x.z, x.w));
  };
  auto loadT = [&](int kt, uint2* a2, float4* b4) {
    int kk = kt * BK + kq0 * 4;
    a2[0] = loadA1(fi0, kk);
    a2[1] = loadA1(fi0 + 64, kk);
    b4[0] = *(const float4*)(Wr + (size_t)fi0 * K + kk);
    b4[1] = *(const float4*)(Wr + (size_t)(fi0 + 64) * K + kk);
  };
  auto storeT = [&](const uint2* a2, const float4* b4) {
#pragma unroll
    for (int v = 0; v < 2; v++) {
      int i = fi0 + v * 64;
      As[i][ppos(2 * kq0)] = a2[v].x;
      As[i][ppos(2 * kq0 + 1)] = a2[v].y;
      float4 y = b4[v];
      Bs[i][ppos(2 * kq0)] = pack_bf16(y.x, y.y);
      Bs[i][ppos(2 * kq0 + 1)] = pack_bf16(y.z, y.w);
    }
  };

  uint2 ra[2];
  float4 rb[2];
  loadT(0, ra, rb);
  storeT(ra, rb);
  __syncthreads();

  for (int kt = 0; kt < KT; kt++) {
    uint2 na[2];
    float4 nb[2];
    if (kt + 1 < KT) loadT(kt + 1, na, nb);
    unsigned af[MT][4], bf[NT][2];
#pragma unroll
    for (int mt = 0; mt < MT; mt++) {
      int m = wm * 32 + mt * 16 + r;
      uint2 lo = *(const uint2*)&As[m][2 * c];
      uint2 hi = *(const uint2*)&As[m + 8][2 * c];
      af[mt][0] = lo.x; af[mt][2] = lo.y;
      af[mt][1] = hi.x; af[mt][3] = hi.y;
    }
#pragma unroll
    for (int nt = 0; nt < NT; nt++) {
      int n = wn * 64 + nt * 8 + r;
      uint2 bb = *(const uint2*)&Bs[n][2 * c];
      bf[nt][0] = bb.x; bf[nt][1] = bb.y;
    }
#pragma unroll
    for (int mt = 0; mt < MT; mt++)
#pragma unroll
      for (int nt = 0; nt < NT; nt++) mma_bf16(acc[mt][nt], af[mt], bf[nt]);
    if (kt + 1 < KT) {
      __syncthreads();
      storeT(na, nb);
      __syncthreads();
    }
  }
  __syncthreads();

  float ps[4] = {0.f, 0.f, 0.f, 0.f};
#pragma unroll
  for (int nt = 0; nt < NT; nt++) {
#pragma unroll
    for (int j = 0; j < 2; j++) {
      int n = wn * 64 + nt * 8 + 2 * c + j;
      float bb = sBr[n], wp = sWp[n];
#pragma unroll
      for (int mt = 0; mt < MT; mt++) {
        float h0 = tanhf(acc[mt][nt][j] + bb);
        float h1 = tanhf(acc[mt][nt][2 + j] + bb);
        ps[mt * 2 + 0] = fmaf(h0, wp, ps[mt * 2 + 0]);
        ps[mt * 2 + 1] = fmaf(h1, wp, ps[mt * 2 + 1]);
      }
    }
  }
#pragma unroll
  for (int off = 1; off <= 2; off <<= 1)
#pragma unroll
    for (int i = 0; i < 4; i++) ps[i] += __shfl_xor_sync(0xffffffffu, ps[i], off);
  if (c == 0) {
#pragma unroll
    for (int mt = 0; mt < MT; mt++)
#pragma unroll
      for (int hf = 0; hf < 2; hf++)
        red[wm * 32 + mt * 16 + r + hf * 8][wn] = ps[mt * 2 + hf];
  }
  __syncthreads();

  float per = 0.f, val = 0.f;
  if (tid < 128) {
    float p = bp[0] + red[tid][0] + red[tid][1];
    size_t row = (size_t)bm + tid;
    out_probs[row] = 1.f / (1.f + expf(-p));
    float tg = target[row];
    if (tg >= 0.f) {
      per = fmaxf(p, 0.f) - p * tg + log1pf(expf(-fabsf(p)));
      val = 1.f;
    }
  }
  __syncthreads();
  if (tid < 128) { sl[tid] = per; sv[tid] = val; }
  __syncthreads();
  for (int s = 64; s > 0; s >>= 1) {
    if (tid < s) { sl[tid] += sl[tid + s]; sv[tid] += sv[tid + s]; }
    __syncthreads();
  }
  if (tid == 0) {
    g_part[2 * blockIdx.y] = sl[0];
    g_part[2 * blockIdx.y + 1] = sv[0];
  }
}

// ---------------- final loss reduction ----------------
__global__ void __launch_bounds__(256) finalize_kernel(float* __restrict__ out) {
  __shared__ float sl[256], sv[256];
  int tid = threadIdx.x;
  float l = 0.f, v = 0.f;
  for (int i = tid; i < BT_ / 128; i += 256) {
    l += g_part[2 * i];
    v += g_part[2 * i + 1];
  }
  sl[tid] = l; sv[tid] = v;
  __syncthreads();
  for (int s = 128; s > 0; s >>= 1) {
    if (tid < s) { sl[tid] += sl[tid + s]; sv[tid] += sv[tid + s]; }
    __syncthreads();
  }
  if (tid == 0) out[0] = sl[0] / fmaxf(sv[0], 1.f);
}

// ---------------- launch ----------------
extern "C" void kernel_launch(void* const* d_in, const int* in_sizes, int n_in,
                              void* d_out, int out_size) {
  const int* q_data = (const int*)d_in[0];
  const int* qa_data = (const int*)d_in[1];
  const float* target = (const float*)d_in[2];
  const float* q_tab = (const float*)d_in[3];
  const float* qa_tab = (const float*)d_in[4];
  const float* Mk = (const float*)d_in[5];
  const float* Mv0 = (const float*)d_in[6];
  const float* We = (const float*)d_in[7];
  const float* be = (const float*)d_in[8];
  const float* Wa = (const float*)d_in[9];
  const float* ba = (const float*)d_in[10];
  const float* Wr = (const float*)d_in[11];
  const float* br = (const float*)d_in[12];
  const float* Wp = (const float*)d_in[13];
  const float* bp = (const float*)d_in[14];
  float* out = (float*)d_out;

  logits_softmax_bf16<<<BT_ / 128, 256>>>(q_tab, q_data, Mk);
  gemm_ea_bf16<<<dim3(4, BT_ / 128), 256>>>(qa_tab, qa_data, We, be, Wa, ba);
  scan_kernel<<<B_, 256>>>(Mv0, q_data);
  final_bf16<<<dim3(1, BT_ / 128), 256>>>(q_tab, q_data, Wr, br, Wp, bp, target,
                                          out + 1);
  finalize_kernel<<<1, 256>>>(out);
}

// round 6
// speedup vs baseline: 1.1363x; 1.0980x over previous
#include <cuda_runtime.h>
#include <cuda_bf16.h>
#include <math.h>

#define B_  256
#define T_  500
#define BT_ 128000
#define DK_ 128
#define DV_ 256
#define M_  50
#define LW_ 52    // padded row stride of softmax weights
#define KF_ 384   // DV + DK
#define LDT 24    // smem tile row stride in bf16 (48 bytes: conflict-free ldmatrix)

// ---------------- scratch ----------------
__device__ unsigned g_EA[(size_t)BT_ * DV_];          // (e,a) bf16x2 per (row,d)
__device__ float g_Wt[(size_t)BT_ * LW_];
__device__ __nv_bfloat16 g_READ[(size_t)BT_ * DV_];   // scan output, bf16
__device__ float g_part[2 * (BT_ / 128)];

// ---------------- helpers ----------------
__device__ __forceinline__ unsigned pack_bf16(float lo, float hi) {
  unsigned r;
  asm("cvt.rn.bf16x2.f32 %0, %1, %2;" : "=r"(r) : "f"(hi), "f"(lo));
  return r;
}
__device__ __forceinline__ void mma_bf16(float* c, const unsigned* a, const unsigned* b) {
  asm volatile(
      "mma.sync.aligned.m16n8k16.row.col.f32.bf16.bf16.f32 "
      "{%0,%1,%2,%3}, {%4,%5,%6,%7}, {%8,%9}, {%0,%1,%2,%3};\n"
      : "+f"(c[0]), "+f"(c[1]), "+f"(c[2]), "+f"(c[3])
      : "r"(a[0]), "r"(a[1]), "r"(a[2]), "r"(a[3]), "r"(b[0]), "r"(b[1]));
}
__device__ __forceinline__ void ldsm_x4(unsigned& r0, unsigned& r1, unsigned& r2,
                                        unsigned& r3, unsigned addr) {
  asm volatile(
      "ldmatrix.sync.aligned.m8n8.x4.shared.b16 {%0,%1,%2,%3}, [%4];"
      : "=r"(r0), "=r"(r1), "=r"(r2), "=r"(r3) : "r"(addr));
}
__device__ __forceinline__ unsigned smem_u32(const void* p) {
  return (unsigned)__cvta_generic_to_shared(p);
}
// old ppos permutation (kept for logits kernel)
__host__ __device__ __forceinline__ constexpr int ppos(int j) {
  return 2 * (j & 3) + (j >> 2);
}
__device__ __forceinline__ unsigned long long pack2(float lo, float hi) {
  unsigned long long r;
  asm("mov.b64 %0, {%1,%2};" : "=l"(r) : "f"(lo), "f"(hi));
  return r;
}
__device__ __forceinline__ unsigned long long fma2(unsigned long long a,
                                                   unsigned long long b,
                                                   unsigned long long c) {
  unsigned long long d;
  asm("fma.rn.f32x2 %0, %1, %2, %3;" : "=l"(d) : "l"(a), "l"(b), "l"(c));
  return d;
}
__device__ __forceinline__ float2 unpack2(unsigned long long v) {
  float2 f;
  asm("mov.b64 {%0,%1}, %2;" : "=f"(f.x), "=f"(f.y) : "l"(v));
  return f;
}

// ================= bf16 GEMM: E and A in ONE block (ldmatrix + 2-stage) =====
// Block: 128 rows x 64-col slab; computes e=sigmoid(qa@We^T+be), a=tanh(qa@Wa^T+ba),
// stores pack(e,a) to g_EA.
__global__ void __launch_bounds__(256) gemm_ea_bf16(
    const float* __restrict__ tab, const int* __restrict__ idx,
    const float* __restrict__ We, const float* __restrict__ be,
    const float* __restrict__ Wa, const float* __restrict__ ba) {
  constexpr int BM = 128, BK = 16, K = 256, KT = K / BK;
  constexpr int MT = 4, NT = 2;  // per-matrix warp tile 64x16, warp grid 2x4
  constexpr int STG = BM * LDT;  // bf16 per stage

  __shared__ __align__(16) __nv_bfloat16 As[2 * STG];
  __shared__ __align__(16) __nv_bfloat16 Bs[2 * STG];  // rows 0-63 E, 64-127 A
  __shared__ int rowA[BM];

  const int tid = threadIdx.x;
  const int wid = tid >> 5, lane = tid & 31;
  const int wm = wid >> 2, wn = wid & 3;  // 2 x 4
  const int r = lane >> 2, c = lane & 3;
  const int bm = blockIdx.y * BM;
  const int nrow0 = blockIdx.x * 64;

  for (int i = tid; i < BM; i += 256) rowA[i] = idx[bm + i];
  __syncthreads();

  float accE[MT][NT][4], accA[MT][NT][4];
#pragma unroll
  for (int i = 0; i < MT; i++)
#pragma unroll
    for (int j = 0; j < NT; j++)
#pragma unroll
      for (int q = 0; q < 4; q++) { accE[i][j][q] = 0.f; accA[i][j][q] = 0.f; }

  const int fi0 = tid >> 2, kq0 = tid & 3;  // fi0: 0..63

  // ldmatrix per-thread source offsets (in bf16 units)
  const unsigned aBase = smem_u32(As);
  const unsigned bBase = smem_u32(Bs);
  const int aRow = wm * 64 + (lane & 15);
  const int aColB = (lane & 16) ? 16 : 0;  // bytes
  const int bRowE = wn * 16 + ((lane >> 4) << 3) + (lane & 7);
  const int bColB = (lane & 8) ? 16 : 0;

  auto loadT = [&](int kt, float4* a4, float4* b4) {
    int k0 = kt * BK + kq0 * 4;
    a4[0] = *(const float4*)(tab + (size_t)rowA[fi0] * K + k0);
    a4[1] = *(const float4*)(tab + (size_t)rowA[fi0 + 64] * K + k0);
    b4[0] = *(const float4*)(We + (size_t)(nrow0 + fi0) * K + k0);
    b4[1] = *(const float4*)(Wa + (size_t)(nrow0 + fi0) * K + k0);
  };
  auto storeT = [&](int stg, const float4* a4, const float4* b4) {
    __nv_bfloat16* as = As + stg * STG;
    __nv_bfloat16* bs = Bs + stg * STG;
    uint2 v;
    v = make_uint2(pack_bf16(a4[0].x, a4[0].y), pack_bf16(a4[0].z, a4[0].w));
    *(uint2*)(as + fi0 * LDT + kq0 * 4) = v;
    v = make_uint2(pack_bf16(a4[1].x, a4[1].y), pack_bf16(a4[1].z, a4[1].w));
    *(uint2*)(as + (fi0 + 64) * LDT + kq0 * 4) = v;
    v = make_uint2(pack_bf16(b4[0].x, b4[0].y), pack_bf16(b4[0].z, b4[0].w));
    *(uint2*)(bs + fi0 * LDT + kq0 * 4) = v;
    v = make_uint2(pack_bf16(b4[1].x, b4[1].y), pack_bf16(b4[1].z, b4[1].w));
    *(uint2*)(bs + (fi0 + 64) * LDT + kq0 * 4) = v;
  };

  float4 ra[2], rb[2];
  loadT(0, ra, rb);
  storeT(0, ra, rb);
  __syncthreads();

  for (int kt = 0; kt < KT; kt++) {
    float4 na[2], nb[2];
    if (kt + 1 < KT) loadT(kt + 1, na, nb);
    const unsigned aS = aBase + (kt & 1) * (STG * 2);
    const unsigned bS = bBase + (kt & 1) * (STG * 2);
    unsigned af[MT][4], bfe[4], bfa[4];
#pragma unroll
    for (int mt = 0; mt < MT; mt++)
      ldsm_x4(af[mt][0], af[mt][1], af[mt][2], af[mt][3],
              aS + (aRow + mt * 16) * (LDT * 2) + aColB);
    ldsm_x4(bfe[0], bfe[1], bfe[2], bfe[3],
            bS + bRowE * (LDT * 2) + bColB);
    ldsm_x4(bfa[0], bfa[1], bfa[2], bfa[3],
            bS + (64 + bRowE) * (LDT * 2) + bColB);
#pragma unroll
    for (int mt = 0; mt < MT; mt++) {
      mma_bf16(accE[mt][0], af[mt], &bfe[0]);
      mma_bf16(accE[mt][1], af[mt], &bfe[2]);
      mma_bf16(accA[mt][0], af[mt], &bfa[0]);
      mma_bf16(accA[mt][1], af[mt], &bfa[2]);
    }
    if (kt + 1 < KT) {
      storeT((kt + 1) & 1, na, nb);
      __syncthreads();
    }
  }

  // epilogue: e=sigmoid, a=tanh, pack (e,a)
#pragma unroll
  for (int mt = 0; mt < MT; mt++) {
#pragma unroll
    for (int nt = 0; nt < NT; nt++) {
      int rowL = wm * 64 + mt * 16 + r;
      int ncol = nrow0 + wn * 16 + nt * 8 + 2 * c;
      float be0 = be[ncol], be1 = be[ncol + 1];
      float ba0 = ba[ncol], ba1 = ba[ncol + 1];
      float e0 = 1.f / (1.f + expf(-(accE[mt][nt][0] + be0)));
      float e1 = 1.f / (1.f + expf(-(accE[mt][nt][1] + be1)));
      float e2 = 1.f / (1.f + expf(-(accE[mt][nt][2] + be0)));
      float e3 = 1.f / (1.f + expf(-(accE[mt][nt][3] + be1)));
      float a0 = tanhf(accA[mt][nt][0] + ba0);
      float a1 = tanhf(accA[mt][nt][1] + ba1);
      float a2 = tanhf(accA[mt][nt][2] + ba0);
      float a3 = tanhf(accA[mt][nt][3] + ba1);
      *(uint2*)(g_EA + (size_t)(bm + rowL) * DV_ + ncol) =
          make_uint2(pack_bf16(e0, a0), pack_bf16(e1, a1));
      *(uint2*)(g_EA + (size_t)(bm + rowL + 8) * DV_ + ncol) =
          make_uint2(pack_bf16(e2, a2), pack_bf16(e3, a3));
    }
  }
}

// ================= bf16 logits GEMM + fused softmax (2-stage) =================
__global__ void __launch_bounds__(256) logits_softmax_bf16(
    const float* __restrict__ q_tab, const int* __restrict__ q_data,
    const float* __restrict__ Mk) {
  constexpr int BM = 128, BK = 16, K = 128, KT = K / BK;
  constexpr int MT = 2, NT = 4;

  __shared__ unsigned As[2][BM][10];
  __shared__ unsigned Bs[2][64][10];
  __shared__ int rowA[BM];
  __shared__ float sLg[BM][65];
  __shared__ float sInv[BM];

  const int tid = threadIdx.x;
  const int wid = tid >> 5, lane = tid & 31;
  const int wm = wid >> 1, wn = wid & 1;
  const int r = lane >> 2, c = lane & 3;
  const int bm = blockIdx.x * BM;

  for (int i = tid; i < BM; i += 256) rowA[i] = q_data[bm + i];
  __syncthreads();

  float acc[MT][NT][4];
#pragma unroll
  for (int i = 0; i < MT; i++)
#pragma unroll
    for (int j = 0; j < NT; j++)
#pragma unroll
      for (int q = 0; q < 4; q++) acc[i][j][q] = 0.f;

  const int fi0 = tid >> 2, kq0 = tid & 3;
  const bool bAct = fi0 < 50;

  auto loadT = [&](int kt, float4* a4, float4* b4) {
    int k0 = kt * BK;
    a4[0] = *(const float4*)(q_tab + (size_t)rowA[fi0] * K + k0 + kq0 * 4);
    a4[1] = *(const float4*)(q_tab + (size_t)rowA[fi0 + 64] * K + k0 + kq0 * 4);
    b4[0] = bAct ? *(const float4*)(Mk + (size_t)fi0 * K + k0 + kq0 * 4)
                 : make_float4(0.f, 0.f, 0.f, 0.f);
  };
  auto storeT = [&](int stg, const float4* a4, const float4* b4) {
#pragma unroll
    for (int v = 0; v < 2; v++) {
      int i = fi0 + v * 64;
      float4 x = a4[v];
      As[stg][i][ppos(2 * kq0)] = pack_bf16(x.x, x.y);
      As[stg][i][ppos(2 * kq0 + 1)] = pack_bf16(x.z, x.w);
    }
    float4 y = b4[0];
    Bs[stg][fi0][ppos(2 * kq0)] = pack_bf16(y.x, y.y);
    Bs[stg][fi0][ppos(2 * kq0 + 1)] = pack_bf16(y.z, y.w);
  };

  float4 ra[2], rb[1];
  loadT(0, ra, rb);
  storeT(0, ra, rb);
  __syncthreads();

  for (int kt = 0; kt < KT; kt++) {
    float4 na[2], nb[1];
    if (kt + 1 < KT) loadT(kt + 1, na, nb);
    const int stg = kt & 1;
    unsigned af[MT][4], bf[NT][2];
#pragma unroll
    for (int mt = 0; mt < MT; mt++) {
      int m = wm * 32 + mt * 16 + r;
      uint2 lo = *(const uint2*)&As[stg][m][2 * c];
      uint2 hi = *(const uint2*)&As[stg][m + 8][2 * c];
      af[mt][0] = lo.x; af[mt][2] = lo.y;
      af[mt][1] = hi.x; af[mt][3] = hi.y;
    }
#pragma unroll
    for (int nt = 0; nt < NT; nt++) {
      int n = wn * 32 + nt * 8 + r;
      uint2 bb = *(const uint2*)&Bs[stg][n][2 * c];
      bf[nt][0] = bb.x; bf[nt][1] = bb.y;
    }
#pragma unroll
    for (int mt = 0; mt < MT; mt++)
#pragma unroll
      for (int nt = 0; nt < NT; nt++) mma_bf16(acc[mt][nt], af[mt], bf[nt]);
    if (kt + 1 < KT) {
      storeT(stg ^ 1, na, nb);
      __syncthreads();
    }
  }

#pragma unroll
  for (int mt = 0; mt < MT; mt++) {
#pragma unroll
    for (int nt = 0; nt < NT; nt++) {
      int rowL = wm * 32 + mt * 16 + r;
      int colL = wn * 32 + nt * 8 + 2 * c;
      sLg[rowL][colL] = acc[mt][nt][0];
      sLg[rowL][colL + 1] = acc[mt][nt][1];
      sLg[rowL + 8][colL] = acc[mt][nt][2];
      sLg[rowL + 8][colL + 1] = acc[mt][nt][3];
    }
  }
  __syncthreads();

  if (tid < BM) {
    float mx = -1e30f;
#pragma unroll 10
    for (int j = 0; j < M_; j++) mx = fmaxf(mx, sLg[tid][j]);
    float s = 0.f;
#pragma unroll 10
    for (int j = 0; j < M_; j++) {
      float ev = expf(sLg[tid][j] - mx);
      sLg[tid][j] = ev;
      s += ev;
    }
    sInv[tid] = 1.f / s;
  }
  __syncthreads();

  for (int f = tid; f < BM * LW_; f += 256) {
    int rowL = f / LW_;
    int j = f - rowL * LW_;
    float v = (j < M_) ? sLg[rowL][j] * sInv[rowL] : 0.f;
    g_Wt[(size_t)(bm + rowL) * LW_ + j] = v;
  }
}

// ---------------- scan: one CTA per batch element, barrier-free ----------------
__global__ void __launch_bounds__(256) scan_kernel(
    const float* __restrict__ Mv0, const int* __restrict__ q_data) {
  const int b = blockIdx.x;
  const int d = threadIdx.x;
  const int wid = d >> 5, lane = d & 31;
  __shared__ __align__(16) float ws_all[8][64];
  float* ws = ws_all[wid];

  unsigned long long mv[M_ / 2];
#pragma unroll
  for (int i = 0; i < M_ / 2; i++)
    mv[i] = pack2(Mv0[(2 * i) * DV_ + d], Mv0[(2 * i + 1) * DV_ + d]);

  const size_t row0 = (size_t)b * T_;
  const __nv_bfloat162* EA = (const __nv_bfloat162*)g_EA;
  float2 ea0 = __bfloat1622float2(EA[row0 * DV_ + d]);
  float e = ea0.x, a = ea0.y;
  int qi = q_data[row0];
  if (lane < 13)
    *(float4*)&ws[lane * 4] = *(const float4*)(g_Wt + row0 * LW_ + lane * 4);

  for (int t = 0; t < T_; t++) {
    const size_t row = row0 + t;
    const size_t rn = row0 + (t + 1 < T_ ? t + 1 : t);
    float2 ean = __bfloat1622float2(EA[rn * DV_ + d]);
    int qi2 = q_data[rn];
    float4 wv;
    if (lane < 13) wv = *(const float4*)(g_Wt + rn * LW_ + lane * 4);

    unsigned long long rd0 = 0ULL, rd1 = 0ULL;
    if (qi >= 1) {
      unsigned long long ne2 = pack2(-e, -e);
      unsigned long long ad2 = pack2(a, a);
#pragma unroll
      for (int j = 0; j < 12; j++) {
        ulonglong2 wp = *(const ulonglong2*)&ws[4 * j];
        rd0 = fma2(wp.x, mv[2 * j], rd0);
        unsigned long long t0 = fma2(mv[2 * j], ne2, ad2);
        mv[2 * j] = fma2(wp.x, t0, mv[2 * j]);
        rd1 = fma2(wp.y, mv[2 * j + 1], rd1);
        unsigned long long t1 = fma2(mv[2 * j + 1], ne2, ad2);
        mv[2 * j + 1] = fma2(wp.y, t1, mv[2 * j + 1]);
      }
      unsigned long long wl = *(const unsigned long long*)&ws[48];
      rd0 = fma2(wl, mv[24], rd0);
      unsigned long long tl = fma2(mv[24], ne2, ad2);
      mv[24] = fma2(wl, tl, mv[24]);
    } else {
#pragma unroll
      for (int j = 0; j < 12; j++) {
        ulonglong2 wp = *(const ulonglong2*)&ws[4 * j];
        rd0 = fma2(wp.x, mv[2 * j], rd0);
        rd1 = fma2(wp.y, mv[2 * j + 1], rd1);
      }
      unsigned long long wl = *(const unsigned long long*)&ws[48];
      rd0 = fma2(wl, mv[24], rd0);
    }
    float2 s0 = unpack2(rd0), s1 = unpack2(rd1);
    g_READ[row * DV_ + d] = __float2bfloat16((s0.x + s0.y) + (s1.x + s1.y));

    if (lane < 13) *(float4*)&ws[lane * 4] = wv;
    e = ean.x; a = ean.y; qi = qi2;
  }
}

// ============ final bf16 GEMM (A=[READ|q_e], ldmatrix + 2-stage) + head ======
__global__ void __launch_bounds__(256) final_bf16(
    const float* __restrict__ q_tab, const int* __restrict__ q_data,
    const float* __restrict__ Wr, const float* __restrict__ br,
    const float* __restrict__ Wp, const float* __restrict__ bp,
    const float* __restrict__ target, float* __restrict__ out_probs) {
  constexpr int BM = 128, BK = 16, K = KF_, KT = K / BK;
  constexpr int MT = 2, NT = 8;  // warp tile 32x64, warp grid 4x2
  constexpr int STG = BM * LDT;

  __shared__ __align__(16) __nv_bfloat16 As[2 * STG];
  __shared__ __align__(16) __nv_bfloat16 Bs[2 * STG];
  __shared__ int rowA[BM];
  __shared__ float sBr[128], sWp[128];
  __shared__ float red[128][2];
  __shared__ float sl[128], sv[128];

  const int tid = threadIdx.x;
  const int wid = tid >> 5, lane = tid & 31;
  const int wm = wid >> 1, wn = wid & 1;  // 4 x 2
  const int r = lane >> 2, c = lane & 3;
  const int bm = blockIdx.y * BM;

  if (tid < 128) { sBr[tid] = br[tid]; sWp[tid] = Wp[tid]; }
  for (int i = tid; i < BM; i += 256) rowA[i] = q_data[bm + i];
  __syncthreads();

  float acc[MT][NT][4];
#pragma unroll
  for (int i = 0; i < MT; i++)
#pragma unroll
    for (int j = 0; j < NT; j++)
#pragma unroll
      for (int q = 0; q < 4; q++) acc[i][j][q] = 0.f;

  const int fi0 = tid >> 2, kq0 = tid & 3;

  const unsigned aBase = smem_u32(As);
  const unsigned bBase = smem_u32(Bs);
  const int aRow = wm * 32 + (lane & 15);
  const int aColB = (lane & 16) ? 16 : 0;
  const int bRow0 = wn * 64 + ((lane >> 4) << 3) + (lane & 7);
  const int bColB = (lane & 8) ? 16 : 0;

  auto loadA1 = [&](int fi, int kk) -> uint2 {
    if (kk < DV_)
      return *(const uint2*)(g_READ + (size_t)(bm + fi) * DV_ + kk);
    float4 x = *(const float4*)(q_tab + (size_t)rowA[fi] * DK_ + (kk - DV_));
    return make_uint2(pack_bf16(x.x, x.y), pack_bf16(x.z, x.w));
  };
  auto loadT = [&](int kt, uint2* a2, float4* b4) {
    int kk = kt * BK + kq0 * 4;
    a2[0] = loadA1(fi0, kk);
    a2[1] = loadA1(fi0 + 64, kk);
    b4[0] = *(const float4*)(Wr + (size_t)fi0 * K + kk);
    b4[1] = *(const float4*)(Wr + (size_t)(fi0 + 64) * K + kk);
  };
  auto storeT = [&](int stg, const uint2* a2, const float4* b4) {
    __nv_bfloat16* as = As + stg * STG;
    __nv_bfloat16* bs = Bs + stg * STG;
    *(uint2*)(as + fi0 * LDT + kq0 * 4) = a2[0];
    *(uint2*)(as + (fi0 + 64) * LDT + kq0 * 4) = a2[1];
    *(uint2*)(bs + fi0 * LDT + kq0 * 4) =
        make_uint2(pack_bf16(b4[0].x, b4[0].y), pack_bf16(b4[0].z, b4[0].w));
    *(uint2*)(bs + (fi0 + 64) * LDT + kq0 * 4) =
        make_uint2(pack_bf16(b4[1].x, b4[1].y), pack_bf16(b4[1].z, b4[1].w));
  };

  uint2 ra[2];
  float4 rb[2];
  loadT(0, ra, rb);
  storeT(0, ra, rb);
  __syncthreads();

  for (int kt = 0; kt < KT; kt++) {
    uint2 na[2];
    float4 nb[2];
    if (kt + 1 < KT) loadT(kt + 1, na, nb);
    const unsigned aS = aBase + (kt & 1) * (STG * 2);
    const unsigned bS = bBase + (kt & 1) * (STG * 2);
    unsigned af[MT][4], bf[NT][2];
#pragma unroll
    for (int mt = 0; mt < MT; mt++)
      ldsm_x4(af[mt][0], af[mt][1], af[mt][2], af[mt][3],
              aS + (aRow + mt * 16) * (LDT * 2) + aColB);
#pragma unroll
    for (int p = 0; p < 4; p++)
      ldsm_x4(bf[2 * p][0], bf[2 * p][1], bf[2 * p + 1][0], bf[2 * p + 1][1],
              bS + (bRow0 + p * 16) * (LDT * 2) + bColB);
#pragma unroll
    for (int mt = 0; mt < MT; mt++)
#pragma unroll
      for (int nt = 0; nt < NT; nt++) mma_bf16(acc[mt][nt], af[mt], bf[nt]);
    if (kt + 1 < KT) {
      storeT((kt + 1) & 1, na, nb);
      __syncthreads();
    }
  }
  __syncthreads();

  float ps[4] = {0.f, 0.f, 0.f, 0.f};
#pragma unroll
  for (int nt = 0; nt < NT; nt++) {
#pragma unroll
    for (int j = 0; j < 2; j++) {
      int n = wn * 64 + nt * 8 + 2 * c + j;
      float bb = sBr[n], wp = sWp[n];
#pragma unroll
      for (int mt = 0; mt < MT; mt++) {
        float h0 = tanhf(acc[mt][nt][j] + bb);
        float h1 = tanhf(acc[mt][nt][2 + j] + bb);
        ps[mt * 2 + 0] = fmaf(h0, wp, ps[mt * 2 + 0]);
        ps[mt * 2 + 1] = fmaf(h1, wp, ps[mt * 2 + 1]);
      }
    }
  }
#pragma unroll
  for (int off = 1; off <= 2; off <<= 1)
#pragma unroll
    for (int i = 0; i < 4; i++) ps[i] += __shfl_xor_sync(0xffffffffu, ps[i], off);
  if (c == 0) {
#pragma unroll
    for (int mt = 0; mt < MT; mt++)
#pragma unroll
      for (int hf = 0; hf < 2; hf++)
        red[wm * 32 + mt * 16 + r + hf * 8][wn] = ps[mt * 2 + hf];
  }
  __syncthreads();

  float per = 0.f, val = 0.f;
  if (tid < 128) {
    float p = bp[0] + red[tid][0] + red[tid][1];
    size_t row = (size_t)bm + tid;
    out_probs[row] = 1.f / (1.f + expf(-p));
    float tg = target[row];
    if (tg >= 0.f) {
      per = fmaxf(p, 0.f) - p * tg + log1pf(expf(-fabsf(p)));
      val = 1.f;
    }
  }
  __syncthreads();
  if (tid < 128) { sl[tid] = per; sv[tid] = val; }
  __syncthreads();
  for (int s = 64; s > 0; s >>= 1) {
    if (tid < s) { sl[tid] += sl[tid + s]; sv[tid] += sv[tid + s]; }
    __syncthreads();
  }
  if (tid == 0) {
    g_part[2 * blockIdx.y] = sl[0];
    g_part[2 * blockIdx.y + 1] = sv[0];
  }
}

// ---------------- final loss reduction ----------------
__global__ void __launch_bounds__(256) finalize_kernel(float* __restrict__ out) {
  __shared__ float sl[256], sv[256];
  int tid = threadIdx.x;
  float l = 0.f, v = 0.f;
  for (int i = tid; i < BT_ / 128; i += 256) {
    l += g_part[2 * i];
    v += g_part[2 * i + 1];
  }
  sl[tid] = l; sv[tid] = v;
  __syncthreads();
  for (int s = 128; s > 0; s >>= 1) {
    if (tid < s) { sl[tid] += sl[tid + s]; sv[tid] += sv[tid + s]; }
    __syncthreads();
  }
  if (tid == 0) out[0] = sl[0] / fmaxf(sv[0], 1.f);
}

// ---------------- launch ----------------
extern "C" void kernel_launch(void* const* d_in, const int* in_sizes, int n_in,
                              void* d_out, int out_size) {
  const int* q_data = (const int*)d_in[0];
  const int* qa_data = (const int*)d_in[1];
  const float* target = (const float*)d_in[2];
  const float* q_tab = (const float*)d_in[3];
  const float* qa_tab = (const float*)d_in[4];
  const float* Mk = (const float*)d_in[5];
  const float* Mv0 = (const float*)d_in[6];
  const float* We = (const float*)d_in[7];
  const float* be = (const float*)d_in[8];
  const float* Wa = (const float*)d_in[9];
  const float* ba = (const float*)d_in[10];
  const float* Wr = (const float*)d_in[11];
  const float* br = (const float*)d_in[12];
  const float* Wp = (const float*)d_in[13];
  const float* bp = (const float*)d_in[14];
  float* out = (float*)d_out;

  logits_softmax_bf16<<<BT_ / 128, 256>>>(q_tab, q_data, Mk);
  gemm_ea_bf16<<<dim3(4, BT_ / 128), 256>>>(qa_tab, qa_data, We, be, Wa, ba);
  scan_kernel<<<B_, 256>>>(Mv0, q_data);
  final_bf16<<<dim3(1, BT_ / 128), 256>>>(q_tab, q_data, Wr, br, Wp, bp, target,
                                          out + 1);
  finalize_kernel<<<1, 256>>>(out);
}

// round 7
// speedup vs baseline: 1.2020x; 1.0578x over previous
#include <cuda_runtime.h>
#include <cuda_bf16.h>
#include <math.h>

#define B_  256
#define T_  500
#define BT_ 128000
#define DK_ 128
#define DV_ 256
#define M_  50
#define LW_ 52
#define KF_ 384
#define LDT 24    // smem row stride bf16 (48B, conflict-free ldmatrix)

#define NQA 100001  // qa_tab rows
#define NQT 50001   // q_tab rows

// ---------------- scratch ----------------
__device__ unsigned g_EA[(size_t)BT_ * DV_];
__device__ float g_Wt[(size_t)BT_ * LW_];
__device__ __nv_bfloat16 g_READ[(size_t)BT_ * DV_];
__device__ float g_part[2 * (BT_ / 128)];
// bf16 pre-converted tables/weights
__device__ __align__(16) __nv_bfloat16 g_qa[(size_t)NQA * DV_];
__device__ __align__(16) __nv_bfloat16 g_qt[(size_t)NQT * DK_];
__device__ __align__(16) __nv_bfloat16 g_We[DV_ * DV_];
__device__ __align__(16) __nv_bfloat16 g_Wa[DV_ * DV_];
__device__ __align__(16) __nv_bfloat16 g_Wr[DK_ * KF_];
__device__ __align__(16) __nv_bfloat16 g_Mkp[64 * DK_];  // zero-padded 64x128

// ---------------- helpers ----------------
__device__ __forceinline__ unsigned pack_bf16(float lo, float hi) {
  unsigned r;
  asm("cvt.rn.bf16x2.f32 %0, %1, %2;" : "=r"(r) : "f"(hi), "f"(lo));
  return r;
}
__device__ __forceinline__ void mma_bf16(float* c, const unsigned* a, const unsigned* b) {
  asm volatile(
      "mma.sync.aligned.m16n8k16.row.col.f32.bf16.bf16.f32 "
      "{%0,%1,%2,%3}, {%4,%5,%6,%7}, {%8,%9}, {%0,%1,%2,%3};\n"
      : "+f"(c[0]), "+f"(c[1]), "+f"(c[2]), "+f"(c[3])
      : "r"(a[0]), "r"(a[1]), "r"(a[2]), "r"(a[3]), "r"(b[0]), "r"(b[1]));
}
__device__ __forceinline__ void ldsm_x4(unsigned& r0, unsigned& r1, unsigned& r2,
                                        unsigned& r3, unsigned addr) {
  asm volatile(
      "ldmatrix.sync.aligned.m8n8.x4.shared.b16 {%0,%1,%2,%3}, [%4];"
      : "=r"(r0), "=r"(r1), "=r"(r2), "=r"(r3) : "r"(addr));
}
__device__ __forceinline__ unsigned smem_u32(const void* p) {
  return (unsigned)__cvta_generic_to_shared(p);
}
__device__ __forceinline__ void cp16(unsigned dst, const void* src) {
  asm volatile("cp.async.cg.shared.global [%0], [%1], 16;" :: "r"(dst), "l"(src));
}
#define CP_COMMIT() asm volatile("cp.async.commit_group;")
#define CP_WAIT1()  asm volatile("cp.async.wait_group 1;")

__device__ __forceinline__ unsigned long long pack2(float lo, float hi) {
  unsigned long long r;
  asm("mov.b64 %0, {%1,%2};" : "=l"(r) : "f"(lo), "f"(hi));
  return r;
}
__device__ __forceinline__ unsigned long long fma2(unsigned long long a,
                                                   unsigned long long b,
                                                   unsigned long long c) {
  unsigned long long d;
  asm("fma.rn.f32x2 %0, %1, %2, %3;" : "=l"(d) : "l"(a), "l"(b), "l"(c));
  return d;
}
__device__ __forceinline__ float2 unpack2(unsigned long long v) {
  float2 f;
  asm("mov.b64 {%0,%1}, %2;" : "=f"(f.x), "=f"(f.y) : "l"(v));
  return f;
}

// ---------------- prep: f32 -> bf16 conversions ----------------
__global__ void __launch_bounds__(256) cvt_kernel(const float* __restrict__ in,
                                                  __nv_bfloat16* __restrict__ out,
                                                  int n4) {
  int i = blockIdx.x * 256 + threadIdx.x;
  if (i < n4) {
    float4 v = ((const float4*)in)[i];
    ((uint2*)out)[i] = make_uint2(pack_bf16(v.x, v.y), pack_bf16(v.z, v.w));
  }
}
__global__ void __launch_bounds__(256) mkpad_kernel(const float* __restrict__ Mk) {
  int i = blockIdx.x * 256 + threadIdx.x;  // 2048 iters of 4 elems
  float4 v = (i < (M_ * DK_) / 4) ? ((const float4*)Mk)[i]
                                  : make_float4(0.f, 0.f, 0.f, 0.f);
  ((uint2*)g_Mkp)[i] = make_uint2(pack_bf16(v.x, v.y), pack_bf16(v.z, v.w));
}

// ================= gemm_ea: cp.async 3-stage, E+A one block =================
__global__ void __launch_bounds__(256) gemm_ea_bf16(
    const int* __restrict__ idx,
    const float* __restrict__ be, const float* __restrict__ ba) {
  constexpr int BK = 16, KT = DV_ / BK;
  constexpr int MT = 4;
  constexpr int STGB = 128 * LDT * 2;  // stage bytes = 6144

  __shared__ __align__(16) __nv_bfloat16 As[3 * 128 * LDT];
  __shared__ __align__(16) __nv_bfloat16 Bs[3 * 128 * LDT];  // 0-63 E, 64-127 A
  __shared__ int rowA[128];

  const int tid = threadIdx.x;
  const int wid = tid >> 5, lane = tid & 31;
  const int wm = wid >> 2, wn = wid & 3;
  const int r = lane >> 2, c = lane & 3;
  const int bm = blockIdx.y * 128;
  const int nrow0 = blockIdx.x * 64;

  for (int i = tid; i < 128; i += 256) rowA[i] = idx[bm + i];
  __syncthreads();

  float accE[MT][2][4], accA[MT][2][4];
#pragma unroll
  for (int i = 0; i < MT; i++)
#pragma unroll
    for (int j = 0; j < 2; j++)
#pragma unroll
      for (int q = 0; q < 4; q++) { accE[i][j][q] = 0.f; accA[i][j][q] = 0.f; }

  const unsigned aBase = smem_u32(As);
  const unsigned bBase = smem_u32(Bs);
  const int gRow = tid >> 1, gHalf = tid & 1;
  const __nv_bfloat16* aSrc = g_qa + (size_t)rowA[gRow] * DV_ + gHalf * 8;
  const __nv_bfloat16* bSrc =
      (gRow < 64) ? g_We + (size_t)(nrow0 + gRow) * DV_ + gHalf * 8
                  : g_Wa + (size_t)(nrow0 + gRow - 64) * DV_ + gHalf * 8;
  const unsigned aDst0 = aBase + gRow * 48 + gHalf * 16;
  const unsigned bDst0 = bBase + gRow * 48 + gHalf * 16;

  auto issueT = [&](int kt, int stg) {
    cp16(aDst0 + stg * STGB, aSrc + kt * BK);
    cp16(bDst0 + stg * STGB, bSrc + kt * BK);
    CP_COMMIT();
  };

  issueT(0, 0);
  issueT(1, 1);
  CP_WAIT1();
  __syncthreads();

  const int aRow = wm * 64 + (lane & 15);
  const int aColB = (lane & 16) ? 16 : 0;
  const int bRowE = wn * 16 + ((lane >> 4) << 3) + (lane & 7);
  const int bColB = (lane & 8) ? 16 : 0;

  for (int kt = 0; kt < KT; kt++) {
    const unsigned aS = aBase + (kt % 3) * STGB;
    const unsigned bS = bBase + (kt % 3) * STGB;
    unsigned af[MT][4], bfe[4], bfa[4];
#pragma unroll
    for (int mt = 0; mt < MT; mt++)
      ldsm_x4(af[mt][0], af[mt][1], af[mt][2], af[mt][3],
              aS + (aRow + mt * 16) * 48 + aColB);
    ldsm_x4(bfe[0], bfe[1], bfe[2], bfe[3], bS + bRowE * 48 + bColB);
    ldsm_x4(bfa[0], bfa[1], bfa[2], bfa[3], bS + (64 + bRowE) * 48 + bColB);
#pragma unroll
    for (int mt = 0; mt < MT; mt++) {
      mma_bf16(accE[mt][0], af[mt], &bfe[0]);
      mma_bf16(accE[mt][1], af[mt], &bfe[2]);
      mma_bf16(accA[mt][0], af[mt], &bfa[0]);
      mma_bf16(accA[mt][1], af[mt], &bfa[2]);
    }
    int nk = (kt + 2 < KT) ? kt + 2 : KT - 1;
    issueT(nk, (kt + 2) % 3);
    CP_WAIT1();
    __syncthreads();
  }

#pragma unroll
  for (int mt = 0; mt < MT; mt++) {
#pragma unroll
    for (int nt = 0; nt < 2; nt++) {
      int rowL = wm * 64 + mt * 16 + r;
      int ncol = nrow0 + wn * 16 + nt * 8 + 2 * c;
      float be0 = be[ncol], be1 = be[ncol + 1];
      float ba0 = ba[ncol], ba1 = ba[ncol + 1];
      float e0 = 1.f / (1.f + expf(-(accE[mt][nt][0] + be0)));
      float e1 = 1.f / (1.f + expf(-(accE[mt][nt][1] + be1)));
      float e2 = 1.f / (1.f + expf(-(accE[mt][nt][2] + be0)));
      float e3 = 1.f / (1.f + expf(-(accE[mt][nt][3] + be1)));
      float a0 = tanhf(accA[mt][nt][0] + ba0);
      float a1 = tanhf(accA[mt][nt][1] + ba1);
      float a2 = tanhf(accA[mt][nt][2] + ba0);
      float a3 = tanhf(accA[mt][nt][3] + ba1);
      *(uint2*)(g_EA + (size_t)(bm + rowL) * DV_ + ncol) =
          make_uint2(pack_bf16(e0, a0), pack_bf16(e1, a1));
      *(uint2*)(g_EA + (size_t)(bm + rowL + 8) * DV_ + ncol) =
          make_uint2(pack_bf16(e2, a2), pack_bf16(e3, a3));
    }
  }
}

// ================= logits GEMM + softmax: cp.async 3-stage =================
__global__ void __launch_bounds__(256) logits_softmax_bf16(
    const int* __restrict__ q_data) {
  constexpr int BK = 16, KT = DK_ / BK;
  constexpr int MT = 2, NT = 4;
  constexpr int STGA = 128 * LDT * 2;  // 6144
  constexpr int STGB = 64 * LDT * 2;   // 3072

  __shared__ __align__(16) __nv_bfloat16 As[3 * 128 * LDT];
  __shared__ __align__(16) __nv_bfloat16 Bs[3 * 64 * LDT];
  __shared__ int rowA[128];
  __shared__ float sLg[128][65];
  __shared__ float sInv[128];

  const int tid = threadIdx.x;
  const int wid = tid >> 5, lane = tid & 31;
  const int wm = wid >> 1, wn = wid & 1;
  const int r = lane >> 2, c = lane & 3;
  const int bm = blockIdx.x * 128;

  for (int i = tid; i < 128; i += 256) rowA[i] = q_data[bm + i];
  __syncthreads();

  float acc[MT][NT][4];
#pragma unroll
  for (int i = 0; i < MT; i++)
#pragma unroll
    for (int j = 0; j < NT; j++)
#pragma unroll
      for (int q = 0; q < 4; q++) acc[i][j][q] = 0.f;

  const unsigned aBase = smem_u32(As);
  const unsigned bBase = smem_u32(Bs);
  const int gRow = tid >> 1, gHalf = tid & 1;
  const __nv_bfloat16* aSrc = g_qt + (size_t)rowA[gRow] * DK_ + gHalf * 8;
  const __nv_bfloat16* bSrc = g_Mkp + (size_t)gRow * DK_ + gHalf * 8;  // tid<128
  const unsigned aDst0 = aBase + gRow * 48 + gHalf * 16;
  const unsigned bDst0 = bBase + gRow * 48 + gHalf * 16;

  auto issueT = [&](int kt, int stg) {
    cp16(aDst0 + stg * STGA, aSrc + kt * BK);
    if (tid < 128) cp16(bDst0 + stg * STGB, bSrc + kt * BK);
    CP_COMMIT();
  };

  issueT(0, 0);
  issueT(1, 1);
  CP_WAIT1();
  __syncthreads();

  const int aRow = wm * 32 + (lane & 15);
  const int aColB = (lane & 16) ? 16 : 0;
  const int bRow0 = wn * 32 + ((lane >> 4) << 3) + (lane & 7);
  const int bColB = (lane & 8) ? 16 : 0;

  for (int kt = 0; kt < KT; kt++) {
    const unsigned aS = aBase + (kt % 3) * STGA;
    const unsigned bS = bBase + (kt % 3) * STGB;
    unsigned af[MT][4], bf[NT][2];
#pragma unroll
    for (int mt = 0; mt < MT; mt++)
      ldsm_x4(af[mt][0], af[mt][1], af[mt][2], af[mt][3],
              aS + (aRow + mt * 16) * 48 + aColB);
#pragma unroll
    for (int p = 0; p < 2; p++)
      ldsm_x4(bf[2 * p][0], bf[2 * p][1], bf[2 * p + 1][0], bf[2 * p + 1][1],
              bS + (bRow0 + p * 16) * 48 + bColB);
#pragma unroll
    for (int mt = 0; mt < MT; mt++)
#pragma unroll
      for (int nt = 0; nt < NT; nt++) mma_bf16(acc[mt][nt], af[mt], bf[nt]);
    int nk = (kt + 2 < KT) ? kt + 2 : KT - 1;
    issueT(nk, (kt + 2) % 3);
    CP_WAIT1();
    __syncthreads();
  }

#pragma unroll
  for (int mt = 0; mt < MT; mt++) {
#pragma unroll
    for (int nt = 0; nt < NT; nt++) {
      int rowL = wm * 32 + mt * 16 + r;
      int colL = wn * 32 + nt * 8 + 2 * c;
      sLg[rowL][colL] = acc[mt][nt][0];
      sLg[rowL][colL + 1] = acc[mt][nt][1];
      sLg[rowL + 8][colL] = acc[mt][nt][2];
      sLg[rowL + 8][colL + 1] = acc[mt][nt][3];
    }
  }
  __syncthreads();

  if (tid < 128) {
    float mx = -1e30f;
#pragma unroll 10
    for (int j = 0; j < M_; j++) mx = fmaxf(mx, sLg[tid][j]);
    float s = 0.f;
#pragma unroll 10
    for (int j = 0; j < M_; j++) {
      float ev = expf(sLg[tid][j] - mx);
      sLg[tid][j] = ev;
      s += ev;
    }
    sInv[tid] = 1.f / s;
  }
  __syncthreads();

  for (int f = tid; f < 128 * LW_; f += 256) {
    int rowL = f / LW_;
    int j = f - rowL * LW_;
    float v = (j < M_) ? sLg[rowL][j] * sInv[rowL] : 0.f;
    g_Wt[(size_t)(bm + rowL) * LW_ + j] = v;
  }
}

// ---------------- scan (unchanged) ----------------
__global__ void __launch_bounds__(256) scan_kernel(
    const float* __restrict__ Mv0, const int* __restrict__ q_data) {
  const int b = blockIdx.x;
  const int d = threadIdx.x;
  const int wid = d >> 5, lane = d & 31;
  __shared__ __align__(16) float ws_all[8][64];
  float* ws = ws_all[wid];

  unsigned long long mv[M_ / 2];
#pragma unroll
  for (int i = 0; i < M_ / 2; i++)
    mv[i] = pack2(Mv0[(2 * i) * DV_ + d], Mv0[(2 * i + 1) * DV_ + d]);

  const size_t row0 = (size_t)b * T_;
  const __nv_bfloat162* EA = (const __nv_bfloat162*)g_EA;
  float2 ea0 = __bfloat1622float2(EA[row0 * DV_ + d]);
  float e = ea0.x, a = ea0.y;
  int qi = q_data[row0];
  if (lane < 13)
    *(float4*)&ws[lane * 4] = *(const float4*)(g_Wt + row0 * LW_ + lane * 4);

  for (int t = 0; t < T_; t++) {
    const size_t row = row0 + t;
    const size_t rn = row0 + (t + 1 < T_ ? t + 1 : t);
    float2 ean = __bfloat1622float2(EA[rn * DV_ + d]);
    int qi2 = q_data[rn];
    float4 wv;
    if (lane < 13) wv = *(const float4*)(g_Wt + rn * LW_ + lane * 4);

    unsigned long long rd0 = 0ULL, rd1 = 0ULL;
    if (qi >= 1) {
      unsigned long long ne2 = pack2(-e, -e);
      unsigned long long ad2 = pack2(a, a);
#pragma unroll
      for (int j = 0; j < 12; j++) {
        ulonglong2 wp = *(const ulonglong2*)&ws[4 * j];
        rd0 = fma2(wp.x, mv[2 * j], rd0);
        unsigned long long t0 = fma2(mv[2 * j], ne2, ad2);
        mv[2 * j] = fma2(wp.x, t0, mv[2 * j]);
        rd1 = fma2(wp.y, mv[2 * j + 1], rd1);
        unsigned long long t1 = fma2(mv[2 * j + 1], ne2, ad2);
        mv[2 * j + 1] = fma2(wp.y, t1, mv[2 * j + 1]);
      }
      unsigned long long wl = *(const unsigned long long*)&ws[48];
      rd0 = fma2(wl, mv[24], rd0);
      unsigned long long tl = fma2(mv[24], ne2, ad2);
      mv[24] = fma2(wl, tl, mv[24]);
    } else {
#pragma unroll
      for (int j = 0; j < 12; j++) {
        ulonglong2 wp = *(const ulonglong2*)&ws[4 * j];
        rd0 = fma2(wp.x, mv[2 * j], rd0);
        rd1 = fma2(wp.y, mv[2 * j + 1], rd1);
      }
      unsigned long long wl = *(const unsigned long long*)&ws[48];
      rd0 = fma2(wl, mv[24], rd0);
    }
    float2 s0 = unpack2(rd0), s1 = unpack2(rd1);
    g_READ[row * DV_ + d] = __float2bfloat16((s0.x + s0.y) + (s1.x + s1.y));

    if (lane < 13) *(float4*)&ws[lane * 4] = wv;
    e = ean.x; a = ean.y; qi = qi2;
  }
}

// ============ final GEMM (A=[READ|q_e]) cp.async 3-stage + fused head ======
__global__ void __launch_bounds__(256) final_bf16(
    const int* __restrict__ q_data,
    const float* __restrict__ br, const float* __restrict__ Wp,
    const float* __restrict__ bp, const float* __restrict__ target,
    float* __restrict__ out_probs) {
  constexpr int BK = 16, KT = KF_ / BK;  // 24
  constexpr int MT = 2, NT = 8;
  constexpr int STGB = 128 * LDT * 2;  // 6144

  __shared__ __align__(16) __nv_bfloat16 As[3 * 128 * LDT];
  __shared__ __align__(16) __nv_bfloat16 Bs[3 * 128 * LDT];
  __shared__ int rowA[128];
  __shared__ float sBr[128], sWp[128];
  __shared__ float red[128][2];
  __shared__ float sl[128], sv[128];

  const int tid = threadIdx.x;
  const int wid = tid >> 5, lane = tid & 31;
  const int wm = wid >> 1, wn = wid & 1;
  const int r = lane >> 2, c = lane & 3;
  const int bm = blockIdx.y * 128;

  if (tid < 128) { sBr[tid] = br[tid]; sWp[tid] = Wp[tid]; }
  for (int i = tid; i < 128; i += 256) rowA[i] = q_data[bm + i];
  __syncthreads();

  float acc[MT][NT][4];
#pragma unroll
  for (int i = 0; i < MT; i++)
#pragma unroll
    for (int j = 0; j < NT; j++)
#pragma unroll
      for (int q = 0; q < 4; q++) acc[i][j][q] = 0.f;

  const unsigned aBase = smem_u32(As);
  const unsigned bBase = smem_u32(Bs);
  const int gRow = tid >> 1, gHalf = tid & 1;
  const __nv_bfloat16* aSrcR = g_READ + (size_t)(bm + gRow) * DV_ + gHalf * 8;
  const __nv_bfloat16* aSrcQ = g_qt + (size_t)rowA[gRow] * DK_ + gHalf * 8;
  const __nv_bfloat16* bSrc = g_Wr + (size_t)gRow * KF_ + gHalf * 8;
  const unsigned aDst0 = aBase + gRow * 48 + gHalf * 16;
  const unsigned bDst0 = bBase + gRow * 48 + gHalf * 16;

  auto issueT = [&](int kt, int stg) {
    const __nv_bfloat16* a =
        (kt < 16) ? aSrcR + kt * BK : aSrcQ + (kt - 16) * BK;
    cp16(aDst0 + stg * STGB, a);
    cp16(bDst0 + stg * STGB, bSrc + kt * BK);
    CP_COMMIT();
  };

  issueT(0, 0);
  issueT(1, 1);
  CP_WAIT1();
  __syncthreads();

  const int aRow = wm * 32 + (lane & 15);
  const int aColB = (lane & 16) ? 16 : 0;
  const int bRow0 = wn * 64 + ((lane >> 4) << 3) + (lane & 7);
  const int bColB = (lane & 8) ? 16 : 0;

  for (int kt = 0; kt < KT; kt++) {
    const unsigned aS = aBase + (kt % 3) * STGB;
    const unsigned bS = bBase + (kt % 3) * STGB;
    unsigned af[MT][4], bf[NT][2];
#pragma unroll
    for (int mt = 0; mt < MT; mt++)
      ldsm_x4(af[mt][0], af[mt][1], af[mt][2], af[mt][3],
              aS + (aRow + mt * 16) * 48 + aColB);
#pragma unroll
    for (int p = 0; p < 4; p++)
      ldsm_x4(bf[2 * p][0], bf[2 * p][1], bf[2 * p + 1][0], bf[2 * p + 1][1],
              bS + (bRow0 + p * 16) * 48 + bColB);
#pragma unroll
    for (int mt = 0; mt < MT; mt++)
#pragma unroll
      for (int nt = 0; nt < NT; nt++) mma_bf16(acc[mt][nt], af[mt], bf[nt]);
    int nk = (kt + 2 < KT) ? kt + 2 : KT - 1;
    issueT(nk, (kt + 2) % 3);
    CP_WAIT1();
    __syncthreads();
  }

  float ps[4] = {0.f, 0.f, 0.f, 0.f};
#pragma unroll
  for (int nt = 0; nt < NT; nt++) {
#pragma unroll
    for (int j = 0; j < 2; j++) {
      int n = wn * 64 + nt * 8 + 2 * c + j;
      float bb = sBr[n], wp = sWp[n];
#pragma unroll
      for (int mt = 0; mt < MT; mt++) {
        float h0 = tanhf(acc[mt][nt][j] + bb);
        float h1 = tanhf(acc[mt][nt][2 + j] + bb);
        ps[mt * 2 + 0] = fmaf(h0, wp, ps[mt * 2 + 0]);
        ps[mt * 2 + 1] = fmaf(h1, wp, ps[mt * 2 + 1]);
      }
    }
  }
#pragma unroll
  for (int off = 1; off <= 2; off <<= 1)
#pragma unroll
    for (int i = 0; i < 4; i++) ps[i] += __shfl_xor_sync(0xffffffffu, ps[i], off);
  if (c == 0) {
#pragma unroll
    for (int mt = 0; mt < MT; mt++)
#pragma unroll
      for (int hf = 0; hf < 2; hf++)
        red[wm * 32 + mt * 16 + r + hf * 8][wn] = ps[mt * 2 + hf];
  }
  __syncthreads();

  float per = 0.f, val = 0.f;
  if (tid < 128) {
    float p = bp[0] + red[tid][0] + red[tid][1];
    size_t row = (size_t)bm + tid;
    out_probs[row] = 1.f / (1.f + expf(-p));
    float tg = target[row];
    if (tg >= 0.f) {
      per = fmaxf(p, 0.f) - p * tg + log1pf(expf(-fabsf(p)));
      val = 1.f;
    }
  }
  __syncthreads();
  if (tid < 128) { sl[tid] = per; sv[tid] = val; }
  __syncthreads();
  for (int s = 64; s > 0; s >>= 1) {
    if (tid < s) { sl[tid] += sl[tid + s]; sv[tid] += sv[tid + s]; }
    __syncthreads();
  }
  if (tid == 0) {
    g_part[2 * blockIdx.y] = sl[0];
    g_part[2 * blockIdx.y + 1] = sv[0];
  }
}

// ---------------- final loss reduction ----------------
__global__ void __launch_bounds__(256) finalize_kernel(float* __restrict__ out) {
  __shared__ float sl[256], sv[256];
  int tid = threadIdx.x;
  float l = 0.f, v = 0.f;
  for (int i = tid; i < BT_ / 128; i += 256) {
    l += g_part[2 * i];
    v += g_part[2 * i + 1];
  }
  sl[tid] = l; sv[tid] = v;
  __syncthreads();
  for (int s = 128; s > 0; s >>= 1) {
    if (tid < s) { sl[tid] += sl[tid + s]; sv[tid] += sv[tid + s]; }
    __syncthreads();
  }
  if (tid == 0) out[0] = sl[0] / fmaxf(sv[0], 1.f);
}

// ---------------- launch ----------------
extern "C" void kernel_launch(void* const* d_in, const int* in_sizes, int n_in,
                              void* d_out, int out_size) {
  const int* q_data = (const int*)d_in[0];
  const int* qa_data = (const int*)d_in[1];
  const float* target = (const float*)d_in[2];
  const float* q_tab = (const float*)d_in[3];
  const float* qa_tab = (const float*)d_in[4];
  const float* Mk = (const float*)d_in[5];
  const float* Mv0 = (const float*)d_in[6];
  const float* be = (const float*)d_in[8];
  const float* We = (const float*)d_in[7];
  const float* Wa = (const float*)d_in[9];
  const float* ba = (const float*)d_in[10];
  const float* Wr = (const float*)d_in[11];
  const float* br = (const float*)d_in[12];
  const float* Wp = (const float*)d_in[13];
  const float* bp = (const float*)d_in[14];
  float* out = (float*)d_out;

  __nv_bfloat16 *pqa, *pqt, *pWe, *pWa, *pWr;
  cudaGetSymbolAddress((void**)&pqa, g_qa);
  cudaGetSymbolAddress((void**)&pqt, g_qt);
  cudaGetSymbolAddress((void**)&pWe, g_We);
  cudaGetSymbolAddress((void**)&pWa, g_Wa);
  cudaGetSymbolAddress((void**)&pWr, g_Wr);

  int n4;
  n4 = (NQA * DV_) / 4;
  cvt_kernel<<<(n4 + 255) / 256, 256>>>(qa_tab, pqa, n4);
  n4 = (NQT * DK_) / 4;
  cvt_kernel<<<(n4 + 255) / 256, 256>>>(q_tab, pqt, n4);
  n4 = (DV_ * DV_) / 4;
  cvt_kernel<<<(n4 + 255) / 256, 256>>>(We, pWe, n4);
  cvt_kernel<<<(n4 + 255) / 256, 256>>>(Wa, pWa, n4);
  n4 = (DK_ * KF_) / 4;
  cvt_kernel<<<(n4 + 255) / 256, 256>>>(Wr, pWr, n4);
  mkpad_kernel<<<(64 * DK_ / 4 + 255) / 256, 256>>>(Mk);

  logits_softmax_bf16<<<BT_ / 128, 256>>>(q_data);
  gemm_ea_bf16<<<dim3(4, BT_ / 128), 256>>>(qa_data, be, ba);
  scan_kernel<<<B_, 256>>>(Mv0, q_data);
  final_bf16<<<dim3(1, BT_ / 128), 256>>>(q_data, br, Wp, bp, target, out + 1);
  finalize_kernel<<<1, 256>>>(out);
}

// round 8
// speedup vs baseline: 1.2559x; 1.0448x over previous
#include <cuda_runtime.h>
#include <cuda_bf16.h>
#include <math.h>

#define B_  256
#define T_  500
#define BT_ 128000
#define DK_ 128
#define DV_ 256
#define M_  50
#define LW_ 52
#define KF_ 384
#define LDT 24    // smem row stride bf16 (48B, conflict-free ldmatrix)

#define NQA 100001  // qa_tab rows
#define NQT 50001   // q_tab rows

// ---------------- scratch ----------------
__device__ unsigned g_EA[(size_t)BT_ * DV_];
__device__ float g_Wt[(size_t)BT_ * LW_];
__device__ __nv_bfloat16 g_READ[(size_t)BT_ * DV_];
__device__ float g_part[2 * (BT_ / 128)];
__device__ __align__(16) __nv_bfloat16 g_qa[(size_t)NQA * DV_];
__device__ __align__(16) __nv_bfloat16 g_qt[(size_t)NQT * DK_];
__device__ __align__(16) __nv_bfloat16 g_We[DV_ * DV_];
__device__ __align__(16) __nv_bfloat16 g_Wa[DV_ * DV_];
__device__ __align__(16) __nv_bfloat16 g_Wr[DK_ * KF_];
__device__ __align__(16) __nv_bfloat16 g_Mkp[64 * DK_];

// ---------------- helpers ----------------
__device__ __forceinline__ unsigned pack_bf16(float lo, float hi) {
  unsigned r;
  asm("cvt.rn.bf16x2.f32 %0, %1, %2;" : "=r"(r) : "f"(hi), "f"(lo));
  return r;
}
__device__ __forceinline__ void mma_bf16(float* c, const unsigned* a, const unsigned* b) {
  asm volatile(
      "mma.sync.aligned.m16n8k16.row.col.f32.bf16.bf16.f32 "
      "{%0,%1,%2,%3}, {%4,%5,%6,%7}, {%8,%9}, {%0,%1,%2,%3};\n"
      : "+f"(c[0]), "+f"(c[1]), "+f"(c[2]), "+f"(c[3])
      : "r"(a[0]), "r"(a[1]), "r"(a[2]), "r"(a[3]), "r"(b[0]), "r"(b[1]));
}
__device__ __forceinline__ void ldsm_x4(unsigned& r0, unsigned& r1, unsigned& r2,
                                        unsigned& r3, unsigned addr) {
  asm volatile(
      "ldmatrix.sync.aligned.m8n8.x4.shared.b16 {%0,%1,%2,%3}, [%4];"
      : "=r"(r0), "=r"(r1), "=r"(r2), "=r"(r3) : "r"(addr));
}
__device__ __forceinline__ unsigned smem_u32(const void* p) {
  return (unsigned)__cvta_generic_to_shared(p);
}
__device__ __forceinline__ void cp16(unsigned dst, const void* src) {
  asm volatile("cp.async.cg.shared.global [%0], [%1], 16;" :: "r"(dst), "l"(src));
}
#define CP_COMMIT() asm volatile("cp.async.commit_group;")
#define CP_WAIT1()  asm volatile("cp.async.wait_group 1;")

__device__ __forceinline__ unsigned long long pack2(float lo, float hi) {
  unsigned long long r;
  asm("mov.b64 %0, {%1,%2};" : "=l"(r) : "f"(lo), "f"(hi));
  return r;
}
__device__ __forceinline__ unsigned long long fma2(unsigned long long a,
                                                   unsigned long long b,
                                                   unsigned long long c) {
  unsigned long long d;
  asm("fma.rn.f32x2 %0, %1, %2, %3;" : "=l"(d) : "l"(a), "l"(b), "l"(c));
  return d;
}
__device__ __forceinline__ float2 unpack2(unsigned long long v) {
  float2 f;
  asm("mov.b64 {%0,%1}, %2;" : "=f"(f.x), "=f"(f.y) : "l"(v));
  return f;
}

// ---------------- prep: f32 -> bf16 ----------------
__global__ void __launch_bounds__(256) cvt_kernel(const float* __restrict__ in,
                                                  __nv_bfloat16* __restrict__ out,
                                                  int n4) {
  int i = blockIdx.x * 256 + threadIdx.x;
  if (i < n4) {
    float4 v = ((const float4*)in)[i];
    ((uint2*)out)[i] = make_uint2(pack_bf16(v.x, v.y), pack_bf16(v.z, v.w));
  }
}
// fused: We (16384 f4), Wa (16384), Wr (12288), Mk-pad (2048)
__global__ void __launch_bounds__(256) cvt_wall(const float* __restrict__ We,
                                                const float* __restrict__ Wa,
                                                const float* __restrict__ Wr,
                                                const float* __restrict__ Mk) {
  int i = blockIdx.x * 256 + threadIdx.x;
  const float* src;
  uint2* dst;
  int j = i;
  if (j < 16384) { src = We; dst = (uint2*)g_We; }
  else if ((j -= 16384) < 16384) { src = Wa; dst = (uint2*)g_Wa; }
  else if ((j -= 16384) < 12288) { src = Wr; dst = (uint2*)g_Wr; }
  else if ((j -= 12288) < 2048) {
    float4 v = (j < (M_ * DK_) / 4) ? ((const float4*)Mk)[j]
                                    : make_float4(0.f, 0.f, 0.f, 0.f);
    ((uint2*)g_Mkp)[j] = make_uint2(pack_bf16(v.x, v.y), pack_bf16(v.z, v.w));
    return;
  } else return;
  float4 v = ((const float4*)src)[j];
  dst[j] = make_uint2(pack_bf16(v.x, v.y), pack_bf16(v.z, v.w));
}

// ================= gemm_ea: cp.async 3-stage, E+A one block =================
__global__ void __launch_bounds__(256) gemm_ea_bf16(
    const int* __restrict__ idx,
    const float* __restrict__ be, const float* __restrict__ ba) {
  constexpr int BK = 16, KT = DV_ / BK;
  constexpr int MT = 4;
  constexpr int STGB = 128 * LDT * 2;

  __shared__ __align__(16) __nv_bfloat16 As[3 * 128 * LDT];
  __shared__ __align__(16) __nv_bfloat16 Bs[3 * 128 * LDT];
  __shared__ int rowA[128];

  const int tid = threadIdx.x;
  const int wid = tid >> 5, lane = tid & 31;
  const int wm = wid >> 2, wn = wid & 3;
  const int r = lane >> 2, c = lane & 3;
  const int bm = blockIdx.y * 128;
  const int nrow0 = blockIdx.x * 64;

  for (int i = tid; i < 128; i += 256) rowA[i] = idx[bm + i];
  __syncthreads();

  float accE[MT][2][4], accA[MT][2][4];
#pragma unroll
  for (int i = 0; i < MT; i++)
#pragma unroll
    for (int j = 0; j < 2; j++)
#pragma unroll
      for (int q = 0; q < 4; q++) { accE[i][j][q] = 0.f; accA[i][j][q] = 0.f; }

  const unsigned aBase = smem_u32(As);
  const unsigned bBase = smem_u32(Bs);
  const int gRow = tid >> 1, gHalf = tid & 1;
  const __nv_bfloat16* aSrc = g_qa + (size_t)rowA[gRow] * DV_ + gHalf * 8;
  const __nv_bfloat16* bSrc =
      (gRow < 64) ? g_We + (size_t)(nrow0 + gRow) * DV_ + gHalf * 8
                  : g_Wa + (size_t)(nrow0 + gRow - 64) * DV_ + gHalf * 8;
  const unsigned aDst0 = aBase + gRow * 48 + gHalf * 16;
  const unsigned bDst0 = bBase + gRow * 48 + gHalf * 16;

  auto issueT = [&](int kt, int stg) {
    cp16(aDst0 + stg * STGB, aSrc + kt * BK);
    cp16(bDst0 + stg * STGB, bSrc + kt * BK);
    CP_COMMIT();
  };

  issueT(0, 0);
  issueT(1, 1);
  CP_WAIT1();
  __syncthreads();

  const int aRow = wm * 64 + (lane & 15);
  const int aColB = (lane & 16) ? 16 : 0;
  const int bRowE = wn * 16 + ((lane >> 4) << 3) + (lane & 7);
  const int bColB = (lane & 8) ? 16 : 0;

  for (int kt = 0; kt < KT; kt++) {
    const unsigned aS = aBase + (kt % 3) * STGB;
    const unsigned bS = bBase + (kt % 3) * STGB;
    unsigned af[MT][4], bfe[4], bfa[4];
#pragma unroll
    for (int mt = 0; mt < MT; mt++)
      ldsm_x4(af[mt][0], af[mt][1], af[mt][2], af[mt][3],
              aS + (aRow + mt * 16) * 48 + aColB);
    ldsm_x4(bfe[0], bfe[1], bfe[2], bfe[3], bS + bRowE * 48 + bColB);
    ldsm_x4(bfa[0], bfa[1], bfa[2], bfa[3], bS + (64 + bRowE) * 48 + bColB);
#pragma unroll
    for (int mt = 0; mt < MT; mt++) {
      mma_bf16(accE[mt][0], af[mt], &bfe[0]);
      mma_bf16(accE[mt][1], af[mt], &bfe[2]);
      mma_bf16(accA[mt][0], af[mt], &bfa[0]);
      mma_bf16(accA[mt][1], af[mt], &bfa[2]);
    }
    int nk = (kt + 2 < KT) ? kt + 2 : KT - 1;
    issueT(nk, (kt + 2) % 3);
    CP_WAIT1();
    __syncthreads();
  }

#pragma unroll
  for (int mt = 0; mt < MT; mt++) {
#pragma unroll
    for (int nt = 0; nt < 2; nt++) {
      int rowL = wm * 64 + mt * 16 + r;
      int ncol = nrow0 + wn * 16 + nt * 8 + 2 * c;
      float be0 = be[ncol], be1 = be[ncol + 1];
      float ba0 = ba[ncol], ba1 = ba[ncol + 1];
      float e0 = 1.f / (1.f + expf(-(accE[mt][nt][0] + be0)));
      float e1 = 1.f / (1.f + expf(-(accE[mt][nt][1] + be1)));
      float e2 = 1.f / (1.f + expf(-(accE[mt][nt][2] + be0)));
      float e3 = 1.f / (1.f + expf(-(accE[mt][nt][3] + be1)));
      float a0 = tanhf(accA[mt][nt][0] + ba0);
      float a1 = tanhf(accA[mt][nt][1] + ba1);
      float a2 = tanhf(accA[mt][nt][2] + ba0);
      float a3 = tanhf(accA[mt][nt][3] + ba1);
      *(uint2*)(g_EA + (size_t)(bm + rowL) * DV_ + ncol) =
          make_uint2(pack_bf16(e0, a0), pack_bf16(e1, a1));
      *(uint2*)(g_EA + (size_t)(bm + rowL + 8) * DV_ + ncol) =
          make_uint2(pack_bf16(e2, a2), pack_bf16(e3, a3));
    }
  }
}

// ================= logits GEMM + softmax: cp.async 3-stage =================
__global__ void __launch_bounds__(256) logits_softmax_bf16(
    const int* __restrict__ q_data) {
  constexpr int BK = 16, KT = DK_ / BK;
  constexpr int MT = 2, NT = 4;
  constexpr int STGA = 128 * LDT * 2;
  constexpr int STGB = 64 * LDT * 2;

  __shared__ __align__(16) __nv_bfloat16 As[3 * 128 * LDT];
  __shared__ __align__(16) __nv_bfloat16 Bs[3 * 64 * LDT];
  __shared__ int rowA[128];
  __shared__ float sLg[128][65];
  __shared__ float sInv[128];

  const int tid = threadIdx.x;
  const int wid = tid >> 5, lane = tid & 31;
  const int wm = wid >> 1, wn = wid & 1;
  const int r = lane >> 2, c = lane & 3;
  const int bm = blockIdx.x * 128;

  for (int i = tid; i < 128; i += 256) rowA[i] = q_data[bm + i];
  __syncthreads();

  float acc[MT][NT][4];
#pragma unroll
  for (int i = 0; i < MT; i++)
#pragma unroll
    for (int j = 0; j < NT; j++)
#pragma unroll
      for (int q = 0; q < 4; q++) acc[i][j][q] = 0.f;

  const unsigned aBase = smem_u32(As);
  const unsigned bBase = smem_u32(Bs);
  const int gRow = tid >> 1, gHalf = tid & 1;
  const __nv_bfloat16* aSrc = g_qt + (size_t)rowA[gRow] * DK_ + gHalf * 8;
  const __nv_bfloat16* bSrc = g_Mkp + (size_t)gRow * DK_ + gHalf * 8;
  const unsigned aDst0 = aBase + gRow * 48 + gHalf * 16;
  const unsigned bDst0 = bBase + gRow * 48 + gHalf * 16;

  auto issueT = [&](int kt, int stg) {
    cp16(aDst0 + stg * STGA, aSrc + kt * BK);
    if (tid < 128) cp16(bDst0 + stg * STGB, bSrc + kt * BK);
    CP_COMMIT();
  };

  issueT(0, 0);
  issueT(1, 1);
  CP_WAIT1();
  __syncthreads();

  const int aRow = wm * 32 + (lane & 15);
  const int aColB = (lane & 16) ? 16 : 0;
  const int bRow0 = wn * 32 + ((lane >> 4) << 3) + (lane & 7);
  const int bColB = (lane & 8) ? 16 : 0;

  for (int kt = 0; kt < KT; kt++) {
    const unsigned aS = aBase + (kt % 3) * STGA;
    const unsigned bS = bBase + (kt % 3) * STGB;
    unsigned af[MT][4], bf[NT][2];
#pragma unroll
    for (int mt = 0; mt < MT; mt++)
      ldsm_x4(af[mt][0], af[mt][1], af[mt][2], af[mt][3],
              aS + (aRow + mt * 16) * 48 + aColB);
#pragma unroll
    for (int p = 0; p < 2; p++)
      ldsm_x4(bf[2 * p][0], bf[2 * p][1], bf[2 * p + 1][0], bf[2 * p + 1][1],
              bS + (bRow0 + p * 16) * 48 + bColB);
#pragma unroll
    for (int mt = 0; mt < MT; mt++)
#pragma unroll
      for (int nt = 0; nt < NT; nt++) mma_bf16(acc[mt][nt], af[mt], bf[nt]);
    int nk = (kt + 2 < KT) ? kt + 2 : KT - 1;
    issueT(nk, (kt + 2) % 3);
    CP_WAIT1();
    __syncthreads();
  }

#pragma unroll
  for (int mt = 0; mt < MT; mt++) {
#pragma unroll
    for (int nt = 0; nt < NT; nt++) {
      int rowL = wm * 32 + mt * 16 + r;
      int colL = wn * 32 + nt * 8 + 2 * c;
      sLg[rowL][colL] = acc[mt][nt][0];
      sLg[rowL][colL + 1] = acc[mt][nt][1];
      sLg[rowL + 8][colL] = acc[mt][nt][2];
      sLg[rowL + 8][colL + 1] = acc[mt][nt][3];
    }
  }
  __syncthreads();

  if (tid < 128) {
    float mx = -1e30f;
#pragma unroll 10
    for (int j = 0; j < M_; j++) mx = fmaxf(mx, sLg[tid][j]);
    float s = 0.f;
#pragma unroll 10
    for (int j = 0; j < M_; j++) {
      float ev = expf(sLg[tid][j] - mx);
      sLg[tid][j] = ev;
      s += ev;
    }
    sInv[tid] = 1.f / s;
  }
  __syncthreads();

  for (int f = tid; f < 128 * LW_; f += 256) {
    int rowL = f / LW_;
    int j = f - rowL * LW_;
    float v = (j < M_) ? sLg[rowL][j] * sInv[rowL] : 0.f;
    g_Wt[(size_t)(bm + rowL) * LW_ + j] = v;
  }
}

// ---------------- scan: 4 CTAs x 64 threads per batch (d-split) ----------------
__global__ void __launch_bounds__(64) scan_kernel(
    const float* __restrict__ Mv0, const int* __restrict__ q_data) {
  const int b = blockIdx.x >> 2;
  const int d = ((blockIdx.x & 3) << 6) + threadIdx.x;
  const int wid = threadIdx.x >> 5, lane = threadIdx.x & 31;
  __shared__ __align__(16) float ws_all[2][64];
  float* ws = ws_all[wid];

  unsigned long long mv[M_ / 2];
#pragma unroll
  for (int i = 0; i < M_ / 2; i++)
    mv[i] = pack2(Mv0[(2 * i) * DV_ + d], Mv0[(2 * i + 1) * DV_ + d]);

  const size_t row0 = (size_t)b * T_;
  const __nv_bfloat162* EA = (const __nv_bfloat162*)g_EA;
  float2 ea0 = __bfloat1622float2(EA[row0 * DV_ + d]);
  float e = ea0.x, a = ea0.y;
  int qi = q_data[row0];
  if (lane < 13)
    *(float4*)&ws[lane * 4] = *(const float4*)(g_Wt + row0 * LW_ + lane * 4);

  for (int t = 0; t < T_; t++) {
    const size_t row = row0 + t;
    const size_t rn = row0 + (t + 1 < T_ ? t + 1 : t);
    float2 ean = __bfloat1622float2(EA[rn * DV_ + d]);
    int qi2 = q_data[rn];
    float4 wv;
    if (lane < 13) wv = *(const float4*)(g_Wt + rn * LW_ + lane * 4);

    unsigned long long rd0 = 0ULL, rd1 = 0ULL;
    if (qi >= 1) {
      unsigned long long ne2 = pack2(-e, -e);
      unsigned long long ad2 = pack2(a, a);
#pragma unroll
      for (int j = 0; j < 12; j++) {
        ulonglong2 wp = *(const ulonglong2*)&ws[4 * j];
        rd0 = fma2(wp.x, mv[2 * j], rd0);
        unsigned long long t0 = fma2(mv[2 * j], ne2, ad2);
        mv[2 * j] = fma2(wp.x, t0, mv[2 * j]);
        rd1 = fma2(wp.y, mv[2 * j + 1], rd1);
        unsigned long long t1 = fma2(mv[2 * j + 1], ne2, ad2);
        mv[2 * j + 1] = fma2(wp.y, t1, mv[2 * j + 1]);
      }
      unsigned long long wl = *(const unsigned long long*)&ws[48];
      rd0 = fma2(wl, mv[24], rd0);
      unsigned long long tl = fma2(mv[24], ne2, ad2);
      mv[24] = fma2(wl, tl, mv[24]);
    } else {
#pragma unroll
      for (int j = 0; j < 12; j++) {
        ulonglong2 wp = *(const ulonglong2*)&ws[4 * j];
        rd0 = fma2(wp.x, mv[2 * j], rd0);
        rd1 = fma2(wp.y, mv[2 * j + 1], rd1);
      }
      unsigned long long wl = *(const unsigned long long*)&ws[48];
      rd0 = fma2(wl, mv[24], rd0);
    }
    float2 s0 = unpack2(rd0), s1 = unpack2(rd1);
    g_READ[row * DV_ + d] = __float2bfloat16((s0.x + s0.y) + (s1.x + s1.y));

    if (lane < 13) *(float4*)&ws[lane * 4] = wv;
    e = ean.x; a = ean.y; qi = qi2;
  }
}

// ============ final GEMM (A=[READ|q_e]) cp.async 3-stage + fused head ======
__global__ void __launch_bounds__(256) final_bf16(
    const int* __restrict__ q_data,
    const float* __restrict__ br, const float* __restrict__ Wp,
    const float* __restrict__ bp, const float* __restrict__ target,
    float* __restrict__ out_probs) {
  constexpr int BK = 16, KT = KF_ / BK;
  constexpr int MT = 2, NT = 8;
  constexpr int STGB = 128 * LDT * 2;

  __shared__ __align__(16) __nv_bfloat16 As[3 * 128 * LDT];
  __shared__ __align__(16) __nv_bfloat16 Bs[3 * 128 * LDT];
  __shared__ int rowA[128];
  __shared__ float sBr[128], sWp[128];
  __shared__ float red[128][2];
  __shared__ float sl[128], sv[128];

  const int tid = threadIdx.x;
  const int wid = tid >> 5, lane = tid & 31;
  const int wm = wid >> 1, wn = wid & 1;
  const int r = lane >> 2, c = lane & 3;
  const int bm = blockIdx.y * 128;

  if (tid < 128) { sBr[tid] = br[tid]; sWp[tid] = Wp[tid]; }
  for (int i = tid; i < 128; i += 256) rowA[i] = q_data[bm + i];
  __syncthreads();

  float acc[MT][NT][4];
#pragma unroll
  for (int i = 0; i < MT; i++)
#pragma unroll
    for (int j = 0; j < NT; j++)
#pragma unroll
      for (int q = 0; q < 4; q++) acc[i][j][q] = 0.f;

  const unsigned aBase = smem_u32(As);
  const unsigned bBase = smem_u32(Bs);
  const int gRow = tid >> 1, gHalf = tid & 1;
  const __nv_bfloat16* aSrcR = g_READ + (size_t)(bm + gRow) * DV_ + gHalf * 8;
  const __nv_bfloat16* aSrcQ = g_qt + (size_t)rowA[gRow] * DK_ + gHalf * 8;
  const __nv_bfloat16* bSrc = g_Wr + (size_t)gRow * KF_ + gHalf * 8;
  const unsigned aDst0 = aBase + gRow * 48 + gHalf * 16;
  const unsigned bDst0 = bBase + gRow * 48 + gHalf * 16;

  auto issueT = [&](int kt, int stg) {
    const __nv_bfloat16* a =
        (kt < 16) ? aSrcR + kt * BK : aSrcQ + (kt - 16) * BK;
    cp16(aDst0 + stg * STGB, a);
    cp16(bDst0 + stg * STGB, bSrc + kt * BK);
    CP_COMMIT();
  };

  issueT(0, 0);
  issueT(1, 1);
  CP_WAIT1();
  __syncthreads();

  const int aRow = wm * 32 + (lane & 15);
  const int aColB = (lane & 16) ? 16 : 0;
  const int bRow0 = wn * 64 + ((lane >> 4) << 3) + (lane & 7);
  const int bColB = (lane & 8) ? 16 : 0;

  for (int kt = 0; kt < KT; kt++) {
    const unsigned aS = aBase + (kt % 3) * STGB;
    const unsigned bS = bBase + (kt % 3) * STGB;
    unsigned af[MT][4], bf[NT][2];
#pragma unroll
    for (int mt = 0; mt < MT; mt++)
      ldsm_x4(af[mt][0], af[mt][1], af[mt][2], af[mt][3],
              aS + (aRow + mt * 16) * 48 + aColB);
#pragma unroll
    for (int p = 0; p < 4; p++)
      ldsm_x4(bf[2 * p][0], bf[2 * p][1], bf[2 * p + 1][0], bf[2 * p + 1][1],
              bS + (bRow0 + p * 16) * 48 + bColB);
#pragma unroll
    for (int mt = 0; mt < MT; mt++)
#pragma unroll
      for (int nt = 0; nt < NT; nt++) mma_bf16(acc[mt][nt], af[mt], bf[nt]);
    int nk = (kt + 2 < KT) ? kt + 2 : KT - 1;
    issueT(nk, (kt + 2) % 3);
    CP_WAIT1();
    __syncthreads();
  }

  float ps[4] = {0.f, 0.f, 0.f, 0.f};
#pragma unroll
  for (int nt = 0; nt < NT; nt++) {
#pragma unroll
    for (int j = 0; j < 2; j++) {
      int n = wn * 64 + nt * 8 + 2 * c + j;
      float bb = sBr[n], wp = sWp[n];
#pragma unroll
      for (int mt = 0; mt < MT; mt++) {
        float h0 = tanhf(acc[mt][nt][j] + bb);
        float h1 = tanhf(acc[mt][nt][2 + j] + bb);
        ps[mt * 2 + 0] = fmaf(h0, wp, ps[mt * 2 + 0]);
        ps[mt * 2 + 1] = fmaf(h1, wp, ps[mt * 2 + 1]);
      }
    }
  }
#pragma unroll
  for (int off = 1; off <= 2; off <<= 1)
#pragma unroll
    for (int i = 0; i < 4; i++) ps[i] += __shfl_xor_sync(0xffffffffu, ps[i], off);
  if (c == 0) {
#pragma unroll
    for (int mt = 0; mt < MT; mt++)
#pragma unroll
      for (int hf = 0; hf < 2; hf++)
        red[wm * 32 + mt * 16 + r + hf * 8][wn] = ps[mt * 2 + hf];
  }
  __syncthreads();

  float per = 0.f, val = 0.f;
  if (tid < 128) {
    float p = bp[0] + red[tid][0] + red[tid][1];
    size_t row = (size_t)bm + tid;
    out_probs[row] = 1.f / (1.f + expf(-p));
    float tg = target[row];
    if (tg >= 0.f) {
      per = fmaxf(p, 0.f) - p * tg + log1pf(expf(-fabsf(p)));
      val = 1.f;
    }
  }
  __syncthreads();
  if (tid < 128) { sl[tid] = per; sv[tid] = val; }
  __syncthreads();
  for (int s = 64; s > 0; s >>= 1) {
    if (tid < s) { sl[tid] += sl[tid + s]; sv[tid] += sv[tid + s]; }
    __syncthreads();
  }
  if (tid == 0) {
    g_part[2 * blockIdx.y] = sl[0];
    g_part[2 * blockIdx.y + 1] = sv[0];
  }
}

// ---------------- final loss reduction ----------------
__global__ void __launch_bounds__(256) finalize_kernel(float* __restrict__ out) {
  __shared__ float sl[256], sv[256];
  int tid = threadIdx.x;
  float l = 0.f, v = 0.f;
  for (int i = tid; i < BT_ / 128; i += 256) {
    l += g_part[2 * i];
    v += g_part[2 * i + 1];
  }
  sl[tid] = l; sv[tid] = v;
  __syncthreads();
  for (int s = 128; s > 0; s >>= 1) {
    if (tid < s) { sl[tid] += sl[tid + s]; sv[tid] += sv[tid + s]; }
    __syncthreads();
  }
  if (tid == 0) out[0] = sl[0] / fmaxf(sv[0], 1.f);
}

// ---------------- launch ----------------
extern "C" void kernel_launch(void* const* d_in, const int* in_sizes, int n_in,
                              void* d_out, int out_size) {
  const int* q_data = (const int*)d_in[0];
  const int* qa_data = (const int*)d_in[1];
  const float* target = (const float*)d_in[2];
  const float* q_tab = (const float*)d_in[3];
  const float* qa_tab = (const float*)d_in[4];
  const float* Mk = (const float*)d_in[5];
  const float* Mv0 = (const float*)d_in[6];
  const float* We = (const float*)d_in[7];
  const float* be = (const float*)d_in[8];
  const float* Wa = (const float*)d_in[9];
  const float* ba = (const float*)d_in[10];
  const float* Wr = (const float*)d_in[11];
  const float* br = (const float*)d_in[12];
  const float* Wp = (const float*)d_in[13];
  const float* bp = (const float*)d_in[14];
  float* out = (float*)d_out;

  __nv_bfloat16 *pqa, *pqt;
  cudaGetSymbolAddress((void**)&pqa, g_qa);
  cudaGetSymbolAddress((void**)&pqt, g_qt);

  // launch order chosen so ncu (-s 5 -c 1) profiles scan_kernel (index 5)
  int n4 = (NQA * DV_) / 4;                                     // 0
  cvt_kernel<<<(n4 + 255) / 256, 256>>>(qa_tab, pqa, n4);
  n4 = (NQT * DK_) / 4;                                         // 1
  cvt_kernel<<<(n4 + 255) / 256, 256>>>(q_tab, pqt, n4);
  cvt_wall<<<(47104 + 255) / 256, 256>>>(We, Wa, Wr, Mk);       // 2
  logits_softmax_bf16<<<BT_ / 128, 256>>>(q_data);              // 3
  gemm_ea_bf16<<<dim3(4, BT_ / 128), 256>>>(qa_data, be, ba);   // 4
  scan_kernel<<<B_ * 4, 64>>>(Mv0, q_data);                     // 5  <- profiled
  final_bf16<<<dim3(1, BT_ / 128), 256>>>(q_data, br, Wp, bp, target, out + 1);
  finalize_kernel<<<1, 256>>>(out);
}